// round 1
// baseline (speedup 1.0000x reference)
#include <cuda_runtime.h>
#include <math.h>

// ---------------------------------------------------------------------------
// PointPWC multi-scale loss.
// Inputs (metadata order): pc1_0..3, pc2_0..3, flow_0..3, each [B=2, 3, N].
// Output: 1 float (total weighted loss).
//
// Per scale:
//   A: kNN(p2 -> p2, k=10)  => cv2[n] = (sum_j p2[idx_j] - 10*p2[n]) / 9
//   B: kNN(p1 -> p1, k=10)  => cvw[n] = (sum_j warp[idx_j] - 10*warp[n]) / 9
//                              smooth[n] = sum_{j<9} ||fl[idx_j]-fl[n]|| / 8
//   C: kNN(warp -> p2, k=5) => dist1[n] = d[0];
//                              w_j = 1/(d_j+1e-8), normalized;
//                              inter[n] = sum_j w_j * cv2[idx_j];
//                              curv[n] = ||inter[n] - cvw[n]||^2
//   D: min over warp of d(p2[m], warp)  => dist2[m]
// Total += alpha * ( (sum d1 + sum d2)/B + (sum smooth)/B + 0.3*(sum curv)/B )
// ---------------------------------------------------------------------------

#define TB   128   // threads per block == queries per block
#define TILE 128   // ref points per smem tile (== TB so 1 load/thread)

// scratch (largest scale: 2 * 3 * 8192 floats each)
__device__ float g_cv2[2 * 3 * 8192];
__device__ float g_cvw[2 * 3 * 8192];

// ---------------------------------------------------------------------------

template <int K>
struct TopK {
    float d[K];
    int   i[K];
    __device__ __forceinline__ void init() {
#pragma unroll
        for (int t = 0; t < K; ++t) { d[t] = 3.402823466e38f; i[t] = 0; }
    }
    // Stable insertion: strict '<' everywhere means equal-distance candidates
    // keep earlier (lower) index first, matching jax.lax.top_k tie order since
    // we scan refs in ascending index order.
    __device__ __forceinline__ void push(float nd, int ni) {
        if (nd < d[K - 1]) {
            d[K - 1] = nd; i[K - 1] = ni;
#pragma unroll
            for (int t = K - 1; t > 0; --t) {
                if (d[t] < d[t - 1]) {
                    float td = d[t]; d[t] = d[t - 1]; d[t - 1] = td;
                    int   ti = i[t]; i[t] = i[t - 1]; i[t - 1] = ti;
                }
            }
        }
    }
};

__device__ __forceinline__ float blockReduceSum(float v) {
    __shared__ float sh[TB / 32];
#pragma unroll
    for (int o = 16; o > 0; o >>= 1) v += __shfl_down_sync(0xffffffffu, v, o);
    int lane = threadIdx.x & 31;
    int w    = threadIdx.x >> 5;
    if (lane == 0) sh[w] = v;
    __syncthreads();
    v = 0.0f;
    if (w == 0) {
        if (lane < TB / 32) v = sh[lane];
#pragma unroll
        for (int o = (TB / 64); o > 0; o >>= 1) v += __shfl_down_sync(0xffffffffu, v, o);
    }
    return v;  // valid in thread 0
}

// ---------------------------------------------------------------------------
// Kernel A: kNN(p2->p2, 10) -> cv2
// ---------------------------------------------------------------------------
__global__ void __launch_bounds__(TB)
kA_cv2(const float* __restrict__ p2, int N) {
    const int b = blockIdx.y;
    const int n = blockIdx.x * TB + threadIdx.x;
    const size_t off = (size_t)b * 3 * N;
    const float* px = p2 + off;
    const float* py = px + N;
    const float* pz = py + N;

    const float qx = px[n], qy = py[n], qz = pz[n];

    TopK<10> tk; tk.init();
    __shared__ float4 tile[TILE];

    for (int base = 0; base < N; base += TILE) {
        __syncthreads();
        int t = threadIdx.x;
        tile[t] = make_float4(px[base + t], py[base + t], pz[base + t], 0.0f);
        __syncthreads();
#pragma unroll 8
        for (int j = 0; j < TILE; ++j) {
            float4 r = tile[j];
            float dx = qx - r.x, dy = qy - r.y, dz = qz - r.z;
            float d = fmaf(dx, dx, fmaf(dy, dy, dz * dz));
            tk.push(d, base + j);
        }
    }

    float sx = 0.f, sy = 0.f, sz = 0.f;
#pragma unroll
    for (int j = 0; j < 10; ++j) {
        int i = tk.i[j];
        sx += px[i]; sy += py[i]; sz += pz[i];
    }
    const float inv9 = 1.0f / 9.0f;
    float* o = g_cv2 + off;
    o[n]         = (sx - 10.0f * qx) * inv9;
    o[n + N]     = (sy - 10.0f * qy) * inv9;
    o[n + 2 * N] = (sz - 10.0f * qz) * inv9;
}

// ---------------------------------------------------------------------------
// Kernel B: kNN(p1->p1, 10) -> cvw, smooth (accumulated)
// ---------------------------------------------------------------------------
__global__ void __launch_bounds__(TB)
kB_cvw_smooth(const float* __restrict__ p1, const float* __restrict__ fl,
              int N, float w_sm, float* __restrict__ out) {
    const int b = blockIdx.y;
    const int n = blockIdx.x * TB + threadIdx.x;
    const size_t off = (size_t)b * 3 * N;
    const float* px = p1 + off;
    const float* py = px + N;
    const float* pz = py + N;
    const float* fx = fl + off;
    const float* fy = fx + N;
    const float* fz = fy + N;

    const float qx = px[n], qy = py[n], qz = pz[n];

    TopK<10> tk; tk.init();
    __shared__ float4 tile[TILE];

    for (int base = 0; base < N; base += TILE) {
        __syncthreads();
        int t = threadIdx.x;
        tile[t] = make_float4(px[base + t], py[base + t], pz[base + t], 0.0f);
        __syncthreads();
#pragma unroll 8
        for (int j = 0; j < TILE; ++j) {
            float4 r = tile[j];
            float dx = qx - r.x, dy = qy - r.y, dz = qz - r.z;
            float d = fmaf(dx, dx, fmaf(dy, dy, dz * dz));
            tk.push(d, base + j);
        }
    }

    const float fqx = fx[n], fqy = fy[n], fqz = fz[n];
    const float wqx = qx + fqx, wqy = qy + fqy, wqz = qz + fqz;

    float sx = 0.f, sy = 0.f, sz = 0.f, sm = 0.f;
#pragma unroll
    for (int j = 0; j < 10; ++j) {
        int i = tk.i[j];
        float gfx = fx[i], gfy = fy[i], gfz = fz[i];
        sx += px[i] + gfx;  // warp = p1 + flow
        sy += py[i] + gfy;
        sz += pz[i] + gfz;
        if (j < 9) {  // k9: 9 nearest (sorted ascending) incl. self
            float ddx = gfx - fqx, ddy = gfy - fqy, ddz = gfz - fqz;
            sm += sqrtf(fmaf(ddx, ddx, fmaf(ddy, ddy, ddz * ddz)));
        }
    }
    const float inv9 = 1.0f / 9.0f;
    float* o = g_cvw + off;
    o[n]         = (sx - 10.0f * wqx) * inv9;
    o[n + N]     = (sy - 10.0f * wqy) * inv9;
    o[n + 2 * N] = (sz - 10.0f * wqz) * inv9;

    sm *= 0.125f;  // / 8
    float tot = blockReduceSum(sm);
    if (threadIdx.x == 0) atomicAdd(out, w_sm * tot);
}

// ---------------------------------------------------------------------------
// Kernel C: kNN(warp->p2, 5) -> dist1 + interpolated-curvature loss
// ---------------------------------------------------------------------------
__global__ void __launch_bounds__(TB)
kC_inter(const float* __restrict__ p1, const float* __restrict__ fl,
         const float* __restrict__ p2, int N,
         float w_ch, float w_cv, float* __restrict__ out) {
    const int b = blockIdx.y;
    const int n = blockIdx.x * TB + threadIdx.x;
    const size_t off = (size_t)b * 3 * N;
    const float* p1x = p1 + off; const float* p1y = p1x + N; const float* p1z = p1y + N;
    const float* fx  = fl + off; const float* fy  = fx + N;  const float* fz  = fy + N;
    const float* p2x = p2 + off; const float* p2y = p2x + N; const float* p2z = p2y + N;

    const float qx = p1x[n] + fx[n];
    const float qy = p1y[n] + fy[n];
    const float qz = p1z[n] + fz[n];

    TopK<5> tk; tk.init();
    __shared__ float4 tile[TILE];

    for (int base = 0; base < N; base += TILE) {
        __syncthreads();
        int t = threadIdx.x;
        tile[t] = make_float4(p2x[base + t], p2y[base + t], p2z[base + t], 0.0f);
        __syncthreads();
#pragma unroll 8
        for (int j = 0; j < TILE; ++j) {
            float4 r = tile[j];
            float dx = qx - r.x, dy = qy - r.y, dz = qz - r.z;
            float d = fmaf(dx, dx, fmaf(dy, dy, dz * dz));
            tk.push(d, base + j);
        }
    }

    const float dist1 = tk.d[0];

    float w[5], wsum = 0.f;
#pragma unroll
    for (int j = 0; j < 5; ++j) { w[j] = 1.0f / (tk.d[j] + 1e-8f); wsum += w[j]; }
    const float inv = 1.0f / wsum;

    const float* c2 = g_cv2 + off;
    float ix = 0.f, iy = 0.f, iz = 0.f;
#pragma unroll
    for (int j = 0; j < 5; ++j) {
        int i = tk.i[j];
        float ww = w[j] * inv;
        ix = fmaf(ww, c2[i],         ix);
        iy = fmaf(ww, c2[i + N],     iy);
        iz = fmaf(ww, c2[i + 2 * N], iz);
    }

    const float* cw = g_cvw + off;
    float ex = ix - cw[n], ey = iy - cw[n + N], ez = iz - cw[n + 2 * N];
    float curv = fmaf(ex, ex, fmaf(ey, ey, ez * ez));

    float local = w_ch * dist1 + w_cv * curv;
    float tot = blockReduceSum(local);
    if (threadIdx.x == 0) atomicAdd(out, tot);
}

// ---------------------------------------------------------------------------
// Kernel D: dist2[m] = min_n d(p2[m], warp[n])
// ---------------------------------------------------------------------------
__global__ void __launch_bounds__(TB)
kD_dist2(const float* __restrict__ p1, const float* __restrict__ fl,
         const float* __restrict__ p2, int N,
         float w_ch, float* __restrict__ out) {
    const int b = blockIdx.y;
    const int n = blockIdx.x * TB + threadIdx.x;
    const size_t off = (size_t)b * 3 * N;
    const float* p1x = p1 + off; const float* p1y = p1x + N; const float* p1z = p1y + N;
    const float* fx  = fl + off; const float* fy  = fx + N;  const float* fz  = fy + N;
    const float* p2x = p2 + off; const float* p2y = p2x + N; const float* p2z = p2y + N;

    const float qx = p2x[n], qy = p2y[n], qz = p2z[n];

    float m = 3.402823466e38f;
    __shared__ float4 tile[TILE];

    for (int base = 0; base < N; base += TILE) {
        __syncthreads();
        int t = threadIdx.x;
        tile[t] = make_float4(p1x[base + t] + fx[base + t],
                              p1y[base + t] + fy[base + t],
                              p1z[base + t] + fz[base + t], 0.0f);
        __syncthreads();
#pragma unroll 8
        for (int j = 0; j < TILE; ++j) {
            float4 r = tile[j];
            float dx = qx - r.x, dy = qy - r.y, dz = qz - r.z;
            float d = fmaf(dx, dx, fmaf(dy, dy, dz * dz));
            m = fminf(m, d);
        }
    }

    float tot = blockReduceSum(m);
    if (threadIdx.x == 0) atomicAdd(out, w_ch * tot);
}

// ---------------------------------------------------------------------------

__global__ void kzero(float* out) { out[0] = 0.0f; }

extern "C" void kernel_launch(void* const* d_in, const int* in_sizes, int n_in,
                              void* d_out, int out_size) {
    float* out = (float*)d_out;
    kzero<<<1, 1>>>(out);

    const int   NS[4]    = {8192, 4096, 2048, 1024};
    const float ALPHA[4] = {0.02f, 0.04f, 0.08f, 0.16f};
    const int   B        = 2;

    for (int s = 0; s < 4; ++s) {
        const float* p1 = (const float*)d_in[s];
        const float* p2 = (const float*)d_in[4 + s];
        const float* fl = (const float*)d_in[8 + s];
        const int N = NS[s];
        const float aB = ALPHA[s] / (float)B;   // mean over batch

        dim3 grid(N / TB, B);
        kA_cv2<<<grid, TB>>>(p2, N);
        kB_cvw_smooth<<<grid, TB>>>(p1, fl, N, /*w_sm=*/aB, out);
        kC_inter<<<grid, TB>>>(p1, fl, p2, N, /*w_ch=*/aB, /*w_cv=*/0.3f * aB, out);
        kD_dist2<<<grid, TB>>>(p1, fl, p2, N, /*w_ch=*/aB, out);
    }
}

// round 2
// speedup vs baseline: 1.4265x; 1.4265x over previous
#include <cuda_runtime.h>
#include <math.h>
#include <float.h>

// ---------------------------------------------------------------------------
// PointPWC multi-scale loss — warp-per-query (2 queries/warp) brute-force kNN.
//
// Packed ref arrays hold (x, y, z, |r|^2). Partial distance d' = |r|^2 - 2 q.r
// is monotone in true sqdist per query; true sqdist = d' + |q|^2.
// Each lane keeps a sorted top-K of its 1/32 slice of refs; a K-round warp
// argmin-extract produces the global top-K, leaving neighbor j on lane j.
// ---------------------------------------------------------------------------

#define WPB 4           // warps per block
#define TB  (WPB * 32)
#define QPW 2           // queries per warp

// per-scale offsets into the packed buffers (units of B*N points)
// totals: s0=16384, s1=8192, s2=4096, s3=2048 -> 30720
__device__ float4 g_pp1[30720];
__device__ float4 g_pp2[30720];
__device__ float4 g_pw [30720];
__device__ float4 g_cv2[30720];
__device__ float4 g_cvw[30720];

// ---------------------------------------------------------------------------

template <int K>
__device__ __forceinline__ void pushK(float (&d)[K], int (&ii)[K], float nd, int ni) {
    if (nd < d[K - 1]) {
        d[K - 1] = nd; ii[K - 1] = ni;
#pragma unroll
        for (int t = K - 1; t > 0; --t) {
            if (d[t] < d[t - 1]) {
                float td = d[t]; d[t] = d[t - 1]; d[t - 1] = td;
                int   ti = ii[t]; ii[t] = ii[t - 1]; ii[t - 1] = ti;
            }
        }
    }
}

// scan all N refs for 2 queries; lanes stride the ref array.
template <int K>
__device__ __forceinline__ void scan2(const float4* __restrict__ ref, int N, int lane,
                                      float4 q0, float4 q1,
                                      float (&d0)[K], int (&i0)[K],
                                      float (&d1)[K], int (&i1)[K]) {
    const float a0 = -2.0f * q0.x, b0 = -2.0f * q0.y, c0 = -2.0f * q0.z;
    const float a1 = -2.0f * q1.x, b1 = -2.0f * q1.y, c1 = -2.0f * q1.z;
    for (int base = 0; base < N; base += 128) {
#pragma unroll
        for (int u = 0; u < 4; ++u) {
            int j = base + u * 32 + lane;
            float4 r = __ldg(&ref[j]);
            float t0 = fmaf(a0, r.x, fmaf(b0, r.y, fmaf(c0, r.z, r.w)));
            float t1 = fmaf(a1, r.x, fmaf(b1, r.y, fmaf(c1, r.z, r.w)));
            pushK<K>(d0, i0, t0, j);
            pushK<K>(d1, i1, t1, j);
        }
    }
}

// K-round warp merge: extracts global top-K in ascending order.
// After return: lane r holds (sel_d, sel_i) = r-th nearest; min0 = nearest d' (all lanes).
template <int K>
__device__ __forceinline__ void mergeK(int lane, float (&d)[K], int (&ii)[K],
                                       float& sel_d, int& sel_i, float& min0) {
    sel_d = 0.0f; sel_i = 0; min0 = 0.0f;
#pragma unroll
    for (int r = 0; r < K; ++r) {
        float bd = d[0]; int bi = ii[0];
#pragma unroll
        for (int o = 16; o; o >>= 1) {
            float od = __shfl_xor_sync(0xffffffffu, bd, o);
            int   oi = __shfl_xor_sync(0xffffffffu, bi, o);
            if (od < bd || (od == bd && oi < bi)) { bd = od; bi = oi; }
        }
        if (r == 0) min0 = bd;
        if (lane == r) { sel_d = bd; sel_i = bi; }
        if (d[0] == bd && ii[0] == bi) {  // winning lane advances
#pragma unroll
            for (int t = 0; t < K - 1; ++t) { d[t] = d[t + 1]; ii[t] = ii[t + 1]; }
            d[K - 1] = FLT_MAX; ii[K - 1] = 0x7fffffff;
        }
    }
}

__device__ __forceinline__ float wsum32(float v) {
#pragma unroll
    for (int o = 16; o; o >>= 1) v += __shfl_xor_sync(0xffffffffu, v, o);
    return v;
}
__device__ __forceinline__ float wmin32(float v) {
#pragma unroll
    for (int o = 16; o; o >>= 1) v = fminf(v, __shfl_xor_sync(0xffffffffu, v, o));
    return v;
}

template <int K>
__device__ __forceinline__ void initK(float (&d)[K], int (&ii)[K]) {
#pragma unroll
    for (int t = 0; t < K; ++t) { d[t] = FLT_MAX; ii[t] = 0x7fffffff; }
}

// ---------------------------------------------------------------------------
// Pack kernel: build (x,y,z,|p|^2) for p1, p2, warp=p1+flow.
// ---------------------------------------------------------------------------
__global__ void __launch_bounds__(256)
kPack(const float* __restrict__ p1, const float* __restrict__ p2,
      const float* __restrict__ fl, int soff, int N) {
    int idx = blockIdx.x * 256 + threadIdx.x;
    if (idx >= 2 * N) return;
    int b = idx / N, n = idx - b * N;
    size_t off = (size_t)b * 3 * N;
    const float* P1 = p1 + off;
    const float* P2 = p2 + off;
    const float* F  = fl + off;

    float x = P1[n], y = P1[n + N], z = P1[n + 2 * N];
    g_pp1[soff + idx] = make_float4(x, y, z, fmaf(x, x, fmaf(y, y, z * z)));

    float fx = F[n], fy = F[n + N], fz = F[n + 2 * N];
    float wx = x + fx, wy = y + fy, wz = z + fz;
    g_pw[soff + idx] = make_float4(wx, wy, wz, fmaf(wx, wx, fmaf(wy, wy, wz * wz)));

    float X = P2[n], Y = P2[n + N], Z = P2[n + 2 * N];
    g_pp2[soff + idx] = make_float4(X, Y, Z, fmaf(X, X, fmaf(Y, Y, Z * Z)));
}

// ---------------------------------------------------------------------------
// Kernel A: kNN(p2->p2, 10) -> cv2
// ---------------------------------------------------------------------------
__global__ void __launch_bounds__(TB)
kA(int soff, int N) {
    const int lane = threadIdx.x & 31, w = threadIdx.x >> 5;
    const int base = soff + blockIdx.y * N;
    const int n0 = (blockIdx.x * WPB + w) * QPW;
    const float4* P = g_pp2 + base;
    const float4 q0 = P[n0], q1 = P[n0 + 1];

    float d0[10], d1[10]; int i0[10], i1[10];
    initK<10>(d0, i0); initK<10>(d1, i1);
    scan2<10>(P, N, lane, q0, q1, d0, i0, d1, i1);

#pragma unroll
    for (int qq = 0; qq < 2; ++qq) {
        float sd; int si; float m0;
        if (qq == 0) mergeK<10>(lane, d0, i0, sd, si, m0);
        else         mergeK<10>(lane, d1, i1, sd, si, m0);
        float sx = 0.f, sy = 0.f, sz = 0.f;
        if (lane < 10) { float4 nb = P[si]; sx = nb.x; sy = nb.y; sz = nb.z; }
        sx = wsum32(sx); sy = wsum32(sy); sz = wsum32(sz);
        if (lane == 0) {
            const float4 q = (qq == 0) ? q0 : q1;
            const float inv9 = 1.0f / 9.0f;
            g_cv2[base + n0 + qq] = make_float4((sx - 10.0f * q.x) * inv9,
                                                (sy - 10.0f * q.y) * inv9,
                                                (sz - 10.0f * q.z) * inv9, 0.0f);
        }
    }
}

// ---------------------------------------------------------------------------
// Kernel B: kNN(p1->p1, 10) -> cvw + smoothness
// ---------------------------------------------------------------------------
__global__ void __launch_bounds__(TB)
kB(int soff, int N, float w_sm, float* __restrict__ out) {
    const int lane = threadIdx.x & 31, w = threadIdx.x >> 5;
    const int base = soff + blockIdx.y * N;
    const int n0 = (blockIdx.x * WPB + w) * QPW;
    const float4* P = g_pp1 + base;
    const float4* W = g_pw + base;
    const float4 q0 = P[n0], q1 = P[n0 + 1];

    float d0[10], d1[10]; int i0[10], i1[10];
    initK<10>(d0, i0); initK<10>(d1, i1);
    scan2<10>(P, N, lane, q0, q1, d0, i0, d1, i1);

    float smw = 0.0f;  // warp's smooth contribution (both queries)
#pragma unroll
    for (int qq = 0; qq < 2; ++qq) {
        float sd; int si; float m0;
        if (qq == 0) mergeK<10>(lane, d0, i0, sd, si, m0);
        else         mergeK<10>(lane, d1, i1, sd, si, m0);
        const int n = n0 + qq;
        const float4 qP = (qq == 0) ? q0 : q1;
        const float4 qW = W[n];
        const float flqx = qW.x - qP.x, flqy = qW.y - qP.y, flqz = qW.z - qP.z;
        float sx = 0.f, sy = 0.f, sz = 0.f, sm = 0.f;
        if (lane < 10) {
            float4 nw = W[si];
            sx = nw.x; sy = nw.y; sz = nw.z;
            if (lane < 9) {
                float4 np = P[si];
                float fx = (nw.x - np.x) - flqx;
                float fy = (nw.y - np.y) - flqy;
                float fz = (nw.z - np.z) - flqz;
                sm = sqrtf(fmaf(fx, fx, fmaf(fy, fy, fz * fz)));
            }
        }
        sx = wsum32(sx); sy = wsum32(sy); sz = wsum32(sz); sm = wsum32(sm);
        if (lane == 0) {
            const float inv9 = 1.0f / 9.0f;
            g_cvw[base + n] = make_float4((sx - 10.0f * qW.x) * inv9,
                                          (sy - 10.0f * qW.y) * inv9,
                                          (sz - 10.0f * qW.z) * inv9, 0.0f);
            smw += sm * 0.125f;
        }
    }

    __shared__ float acc;
    if (threadIdx.x == 0) acc = 0.0f;
    __syncthreads();
    if (lane == 0) atomicAdd(&acc, smw);
    __syncthreads();
    if (threadIdx.x == 0) atomicAdd(out, w_sm * acc);
}

// ---------------------------------------------------------------------------
// Kernel C: kNN(warp->p2, 5) -> chamfer dist1 + curvature
// ---------------------------------------------------------------------------
__global__ void __launch_bounds__(TB)
kC(int soff, int N, float w_ch, float w_cv, float* __restrict__ out) {
    const int lane = threadIdx.x & 31, w = threadIdx.x >> 5;
    const int base = soff + blockIdx.y * N;
    const int n0 = (blockIdx.x * WPB + w) * QPW;
    const float4* R = g_pp2 + base;   // refs: p2
    const float4* W = g_pw + base;    // queries: warp
    const float4 q0 = W[n0], q1 = W[n0 + 1];

    float d0[5], d1[5]; int i0[5], i1[5];
    initK<5>(d0, i0); initK<5>(d1, i1);
    scan2<5>(R, N, lane, q0, q1, d0, i0, d1, i1);

    float lossw = 0.0f;
#pragma unroll
    for (int qq = 0; qq < 2; ++qq) {
        float sd; int si; float m0;
        if (qq == 0) mergeK<5>(lane, d0, i0, sd, si, m0);
        else         mergeK<5>(lane, d1, i1, sd, si, m0);
        const float4 q = (qq == 0) ? q0 : q1;
        const float qsq = q.w;
        const float dist1 = m0 + qsq;

        float wgt = 0.0f;
        float4 c = make_float4(0.f, 0.f, 0.f, 0.f);
        if (lane < 5) {
            wgt = 1.0f / ((sd + qsq) + 1e-8f);
            c = g_cv2[base + si];
        }
        float wsum = wsum32(wgt);
        float px = 0.f, py = 0.f, pz = 0.f;
        if (lane < 5) {
            float ww = wgt / wsum;
            px = ww * c.x; py = ww * c.y; pz = ww * c.z;
        }
        float ix = wsum32(px), iy = wsum32(py), iz = wsum32(pz);
        if (lane == 0) {
            float4 cw = g_cvw[base + n0 + qq];
            float ex = ix - cw.x, ey = iy - cw.y, ez = iz - cw.z;
            float curv = fmaf(ex, ex, fmaf(ey, ey, ez * ez));
            lossw += w_ch * dist1 + w_cv * curv;
        }
    }

    __shared__ float acc;
    if (threadIdx.x == 0) acc = 0.0f;
    __syncthreads();
    if (lane == 0) atomicAdd(&acc, lossw);
    __syncthreads();
    if (threadIdx.x == 0) atomicAdd(out, acc);
}

// ---------------------------------------------------------------------------
// Kernel D: dist2[m] = min_n ||p2[m] - warp[n]||^2
// ---------------------------------------------------------------------------
__global__ void __launch_bounds__(TB)
kD(int soff, int N, float w_ch, float* __restrict__ out) {
    const int lane = threadIdx.x & 31, w = threadIdx.x >> 5;
    const int base = soff + blockIdx.y * N;
    const int n0 = (blockIdx.x * WPB + w) * QPW;
    const float4* R = g_pw + base;    // refs: warp
    const float4* Q = g_pp2 + base;   // queries: p2
    const float4 q0 = Q[n0], q1 = Q[n0 + 1];

    const float a0 = -2.0f * q0.x, b0 = -2.0f * q0.y, c0 = -2.0f * q0.z;
    const float a1 = -2.0f * q1.x, b1 = -2.0f * q1.y, c1 = -2.0f * q1.z;
    float m0 = FLT_MAX, m1 = FLT_MAX;
    for (int bb = 0; bb < N; bb += 128) {
#pragma unroll
        for (int u = 0; u < 4; ++u) {
            int j = bb + u * 32 + lane;
            float4 r = __ldg(&R[j]);
            float t0 = fmaf(a0, r.x, fmaf(b0, r.y, fmaf(c0, r.z, r.w)));
            float t1 = fmaf(a1, r.x, fmaf(b1, r.y, fmaf(c1, r.z, r.w)));
            m0 = fminf(m0, t0);
            m1 = fminf(m1, t1);
        }
    }
    m0 = wmin32(m0); m1 = wmin32(m1);

    __shared__ float acc;
    if (threadIdx.x == 0) acc = 0.0f;
    __syncthreads();
    if (lane == 0) atomicAdd(&acc, (m0 + q0.w) + (m1 + q1.w));
    __syncthreads();
    if (threadIdx.x == 0) atomicAdd(out, w_ch * acc);
}

// ---------------------------------------------------------------------------

__global__ void kzero(float* out) { out[0] = 0.0f; }

extern "C" void kernel_launch(void* const* d_in, const int* in_sizes, int n_in,
                              void* d_out, int out_size) {
    float* out = (float*)d_out;
    kzero<<<1, 1>>>(out);

    const int   NS[4]    = {8192, 4096, 2048, 1024};
    const int   SOFF[4]  = {0, 16384, 24576, 28672};
    const float ALPHA[4] = {0.02f, 0.04f, 0.08f, 0.16f};
    const int   B        = 2;

    for (int s = 0; s < 4; ++s) {
        const float* p1 = (const float*)d_in[s];
        const float* p2 = (const float*)d_in[4 + s];
        const float* fl = (const float*)d_in[8 + s];
        kPack<<<(2 * NS[s] + 255) / 256, 256>>>(p1, p2, fl, SOFF[s], NS[s]);
    }

    for (int s = 0; s < 4; ++s) {
        const int N = NS[s];
        const float aB = ALPHA[s] / (float)B;
        dim3 grid(N / (WPB * QPW), B);
        kA<<<grid, TB>>>(SOFF[s], N);
        kB<<<grid, TB>>>(SOFF[s], N, aB, out);
        kD<<<grid, TB>>>(SOFF[s], N, aB, out);
        kC<<<grid, TB>>>(SOFF[s], N, aB, 0.3f * aB, out);
    }
}

// round 3
// speedup vs baseline: 3.3323x; 2.3359x over previous
#include <cuda_runtime.h>
#include <math.h>
#include <float.h>

// ---------------------------------------------------------------------------
// PointPWC multi-scale loss — warp-per-2-queries brute-force kNN with
// warp-global pruning bound + fused launches.
// ---------------------------------------------------------------------------

#define WPB 4
#define TB  (WPB * 32)
#define QPW 2

// packed (x,y,z,|p|^2); per-scale offsets in units of points (B*N per scale)
__device__ float4 g_pp1[30720];
__device__ float4 g_pp2[30720];
__device__ float4 g_pw [30720];
__device__ float4 g_cv2[30720];
__device__ float4 g_cvw[30720];

struct InPtrs { const float* p[12]; };

// ---------------------------------------------------------------------------

template <int K>
__device__ __forceinline__ void pushK(float (&d)[K], int (&ii)[K], float nd, int ni) {
    d[K - 1] = nd; ii[K - 1] = ni;
#pragma unroll
    for (int t = K - 1; t > 0; --t) {
        if (d[t] < d[t - 1]) {
            float td = d[t]; d[t] = d[t - 1]; d[t - 1] = td;
            int   ti = ii[t]; ii[t] = ii[t - 1]; ii[t - 1] = ti;
        }
    }
}

template <int K>
__device__ __forceinline__ void initK(float (&d)[K], int (&ii)[K]) {
#pragma unroll
    for (int t = 0; t < K; ++t) { d[t] = FLT_MAX; ii[t] = 0x7fffffff; }
}

// Upper bound on the global K-th smallest of the union of all lanes' sorted
// lists: K rounds of warp-min extraction on a value-only copy. Lanes tying at
// the round min all advance — that only shrinks the remaining set faster, so
// the round-K min is >= the true K-th (valid upper bound).
template <int K>
__device__ __forceinline__ float boundKth(const float (&d)[K]) {
    float t[K];
#pragma unroll
    for (int j = 0; j < K; ++j) t[j] = d[j];
    float m = FLT_MAX;
#pragma unroll
    for (int r = 0; r < K; ++r) {
        m = t[0];
#pragma unroll
        for (int o = 16; o; o >>= 1) m = fminf(m, __shfl_xor_sync(0xffffffffu, m, o));
        if (t[0] == m) {
#pragma unroll
            for (int j = 0; j < K - 1; ++j) t[j] = t[j + 1];
            t[K - 1] = FLT_MAX;
        }
    }
    return m;
}

// Gated scan: 2 queries per warp, lanes stride refs. Partial distance
// d' = |r|^2 - 2 q.r (monotone in true sqdist per query).
template <int K>
__device__ __forceinline__ void scan2g(const float4* __restrict__ ref, int N, int lane,
                                       float4 q0, float4 q1,
                                       float (&d0)[K], int (&i0)[K],
                                       float (&d1)[K], int (&i1)[K]) {
    const float a0 = -2.0f * q0.x, b0 = -2.0f * q0.y, c0 = -2.0f * q0.z;
    const float a1 = -2.0f * q1.x, b1 = -2.0f * q1.y, c1 = -2.0f * q1.z;
    float bb0 = FLT_MAX, bb1 = FLT_MAX;       // warp-global Kth upper bounds
    float g0 = FLT_MAX, g1 = FLT_MAX;         // combined gates
    const int c1p = N >> 3, c2p = N >> 1;     // checkpoints (multiples of 128)

    for (int base = 0; base < N; base += 128) {
        if (base == c1p || base == c2p) {
            bb0 = boundKth<K>(d0); bb1 = boundKth<K>(d1);
            g0 = fminf(d0[K - 1], bb0);
            g1 = fminf(d1[K - 1], bb1);
        }
#pragma unroll
        for (int u = 0; u < 4; ++u) {
            int j = base + u * 32 + lane;
            float4 r = __ldg(&ref[j]);
            float t0 = fmaf(a0, r.x, fmaf(b0, r.y, fmaf(c0, r.z, r.w)));
            float t1 = fmaf(a1, r.x, fmaf(b1, r.y, fmaf(c1, r.z, r.w)));
            if (t0 < g0) { pushK<K>(d0, i0, t0, j); g0 = fminf(d0[K - 1], bb0); }
            if (t1 < g1) { pushK<K>(d1, i1, t1, j); g1 = fminf(d1[K - 1], bb1); }
        }
    }
}

// K-round warp merge: global top-K ascending; lane r gets the r-th neighbor.
template <int K>
__device__ __forceinline__ void mergeK(int lane, float (&d)[K], int (&ii)[K],
                                       float& sel_d, int& sel_i, float& min0) {
    sel_d = 0.0f; sel_i = 0; min0 = 0.0f;
#pragma unroll
    for (int r = 0; r < K; ++r) {
        float bd = d[0]; int bi = ii[0];
#pragma unroll
        for (int o = 16; o; o >>= 1) {
            float od = __shfl_xor_sync(0xffffffffu, bd, o);
            int   oi = __shfl_xor_sync(0xffffffffu, bi, o);
            if (od < bd || (od == bd && oi < bi)) { bd = od; bi = oi; }
        }
        if (r == 0) min0 = bd;
        if (lane == r) { sel_d = bd; sel_i = bi; }
        if (d[0] == bd && ii[0] == bi) {
#pragma unroll
            for (int t = 0; t < K - 1; ++t) { d[t] = d[t + 1]; ii[t] = ii[t + 1]; }
            d[K - 1] = FLT_MAX; ii[K - 1] = 0x7fffffff;
        }
    }
}

__device__ __forceinline__ float wsum32(float v) {
#pragma unroll
    for (int o = 16; o; o >>= 1) v += __shfl_xor_sync(0xffffffffu, v, o);
    return v;
}
__device__ __forceinline__ float wmin32(float v) {
#pragma unroll
    for (int o = 16; o; o >>= 1) v = fminf(v, __shfl_xor_sync(0xffffffffu, v, o));
    return v;
}

// ---------------------------------------------------------------------------
// Pack: all scales, one launch. Also zeroes the output accumulator.
// ---------------------------------------------------------------------------
__global__ void __launch_bounds__(256)
kPackAll(InPtrs in, float* __restrict__ out) {
    int idx = blockIdx.x * 256 + threadIdx.x;
    if (idx == 0) out[0] = 0.0f;
    if (idx >= 30720) return;
    int s, loc;
    if      (idx < 16384) { s = 0; loc = idx; }
    else if (idx < 24576) { s = 1; loc = idx - 16384; }
    else if (idx < 28672) { s = 2; loc = idx - 24576; }
    else                  { s = 3; loc = idx - 28672; }
    const int NSs[4] = {8192, 4096, 2048, 1024};
    const int N = NSs[s];
    int b = loc >= N;
    int n = loc - (b ? N : 0);
    size_t off = (size_t)b * 3 * N;
    const float* P1 = in.p[s]     + off;
    const float* P2 = in.p[4 + s] + off;
    const float* F  = in.p[8 + s] + off;

    float x = P1[n], y = P1[n + N], z = P1[n + 2 * N];
    g_pp1[idx] = make_float4(x, y, z, fmaf(x, x, fmaf(y, y, z * z)));

    float fx = F[n], fy = F[n + N], fz = F[n + 2 * N];
    float wx = x + fx, wy = y + fy, wz = z + fz;
    g_pw[idx] = make_float4(wx, wy, wz, fmaf(wx, wx, fmaf(wy, wy, wz * wz)));

    float X = P2[n], Y = P2[n + N], Z = P2[n + 2 * N];
    g_pp2[idx] = make_float4(X, Y, Z, fmaf(X, X, fmaf(Y, Y, Z * Z)));
}

// ---------------------------------------------------------------------------
// Fused A/B/D over all scales & batches.
//   type 0 (A): kNN(p2->p2,10) -> cv2
//   type 1 (B): kNN(p1->p1,10) -> cvw + smoothness loss
//   type 2 (D): min over warp of d(p2, warp) -> chamfer dist2
// ---------------------------------------------------------------------------
__global__ void __launch_bounds__(TB)
kABD(float* __restrict__ out) {
    int bx = blockIdx.x;
    int s, rel;
    if      (bx < 6144)  { s = 0; rel = bx; }
    else if (bx < 9216)  { s = 1; rel = bx - 6144; }
    else if (bx < 10752) { s = 2; rel = bx - 9216; }
    else                 { s = 3; rel = bx - 10752; }
    const int   NSs[4]   = {8192, 4096, 2048, 1024};
    const int   SOFFs[4] = {0, 16384, 24576, 28672};
    const float ABs[4]   = {0.01f, 0.02f, 0.04f, 0.08f};
    const int N = NSs[s];
    const int perType = (2 * N) >> 3;       // 8 queries per block
    const int type = rel / perType;
    const int blk = rel - type * perType;

    const int lane = threadIdx.x & 31, w = threadIdx.x >> 5;
    const int qg = blk * 8 + w * 2;
    const int b = qg >= N;
    const int n0 = qg - (b ? N : 0);
    const int base = SOFFs[s] + (b ? N : 0);

    __shared__ float acc;
    if (threadIdx.x == 0) acc = 0.0f;
    __syncthreads();
    float contrib = 0.0f;

    if (type == 0) {
        // ---- A: cv2 from p2 self-kNN ----
        const float4* P = g_pp2 + base;
        const float4 q0 = P[n0], q1 = P[n0 + 1];
        float d0[10], d1[10]; int i0[10], i1[10];
        initK<10>(d0, i0); initK<10>(d1, i1);
        scan2g<10>(P, N, lane, q0, q1, d0, i0, d1, i1);
#pragma unroll
        for (int qq = 0; qq < 2; ++qq) {
            float sd; int si; float m0;
            if (qq == 0) mergeK<10>(lane, d0, i0, sd, si, m0);
            else         mergeK<10>(lane, d1, i1, sd, si, m0);
            float sx = 0.f, sy = 0.f, sz = 0.f;
            if (lane < 10) { float4 nb = P[si]; sx = nb.x; sy = nb.y; sz = nb.z; }
            sx = wsum32(sx); sy = wsum32(sy); sz = wsum32(sz);
            if (lane == 0) {
                const float4 q = (qq == 0) ? q0 : q1;
                const float inv9 = 1.0f / 9.0f;
                g_cv2[base + n0 + qq] = make_float4((sx - 10.0f * q.x) * inv9,
                                                    (sy - 10.0f * q.y) * inv9,
                                                    (sz - 10.0f * q.z) * inv9, 0.0f);
            }
        }
    } else if (type == 1) {
        // ---- B: cvw + smoothness from p1 self-kNN ----
        const float4* P = g_pp1 + base;
        const float4* W = g_pw + base;
        const float4 q0 = P[n0], q1 = P[n0 + 1];
        float d0[10], d1[10]; int i0[10], i1[10];
        initK<10>(d0, i0); initK<10>(d1, i1);
        scan2g<10>(P, N, lane, q0, q1, d0, i0, d1, i1);
#pragma unroll
        for (int qq = 0; qq < 2; ++qq) {
            float sd; int si; float m0;
            if (qq == 0) mergeK<10>(lane, d0, i0, sd, si, m0);
            else         mergeK<10>(lane, d1, i1, sd, si, m0);
            const int n = n0 + qq;
            const float4 qP = (qq == 0) ? q0 : q1;
            const float4 qW = W[n];
            const float flqx = qW.x - qP.x, flqy = qW.y - qP.y, flqz = qW.z - qP.z;
            float sx = 0.f, sy = 0.f, sz = 0.f, sm = 0.f;
            if (lane < 10) {
                float4 nw = W[si];
                sx = nw.x; sy = nw.y; sz = nw.z;
                if (lane < 9) {
                    float4 np = P[si];
                    float fx = (nw.x - np.x) - flqx;
                    float fy = (nw.y - np.y) - flqy;
                    float fz = (nw.z - np.z) - flqz;
                    sm = sqrtf(fmaf(fx, fx, fmaf(fy, fy, fz * fz)));
                }
            }
            sx = wsum32(sx); sy = wsum32(sy); sz = wsum32(sz); sm = wsum32(sm);
            if (lane == 0) {
                const float inv9 = 1.0f / 9.0f;
                g_cvw[base + n] = make_float4((sx - 10.0f * qW.x) * inv9,
                                              (sy - 10.0f * qW.y) * inv9,
                                              (sz - 10.0f * qW.z) * inv9, 0.0f);
                contrib += ABs[s] * sm * 0.125f;
            }
        }
    } else {
        // ---- D: dist2 = min over warp refs of d(p2[m], warp) ----
        const float4* R = g_pw + base;
        const float4* Q = g_pp2 + base;
        const float4 q0 = Q[n0], q1 = Q[n0 + 1];
        const float a0 = -2.0f * q0.x, b0 = -2.0f * q0.y, c0 = -2.0f * q0.z;
        const float a1 = -2.0f * q1.x, b1 = -2.0f * q1.y, c1 = -2.0f * q1.z;
        float m0 = FLT_MAX, m1 = FLT_MAX;
        for (int bb = 0; bb < N; bb += 128) {
#pragma unroll
            for (int u = 0; u < 4; ++u) {
                int j = bb + u * 32 + lane;
                float4 r = __ldg(&R[j]);
                float t0 = fmaf(a0, r.x, fmaf(b0, r.y, fmaf(c0, r.z, r.w)));
                float t1 = fmaf(a1, r.x, fmaf(b1, r.y, fmaf(c1, r.z, r.w)));
                m0 = fminf(m0, t0);
                m1 = fminf(m1, t1);
            }
        }
        m0 = wmin32(m0); m1 = wmin32(m1);
        if (lane == 0) contrib = ABs[s] * ((m0 + q0.w) + (m1 + q1.w));
    }

    if (lane == 0 && contrib != 0.0f) atomicAdd(&acc, contrib);
    __syncthreads();
    if (threadIdx.x == 0 && acc != 0.0f) atomicAdd(out, acc);
}

// ---------------------------------------------------------------------------
// Fused C over all scales & batches: kNN(warp->p2,5) -> chamfer dist1 + curvature.
// ---------------------------------------------------------------------------
__global__ void __launch_bounds__(TB)
kC(float* __restrict__ out) {
    int bx = blockIdx.x;
    int s, blk;
    if      (bx < 2048) { s = 0; blk = bx; }
    else if (bx < 3072) { s = 1; blk = bx - 2048; }
    else if (bx < 3584) { s = 2; blk = bx - 3072; }
    else                { s = 3; blk = bx - 3584; }
    const int   NSs[4]   = {8192, 4096, 2048, 1024};
    const int   SOFFs[4] = {0, 16384, 24576, 28672};
    const float ABs[4]   = {0.01f, 0.02f, 0.04f, 0.08f};
    const int N = NSs[s];
    const float w_ch = ABs[s];
    const float w_cv = 0.3f * ABs[s];

    const int lane = threadIdx.x & 31, w = threadIdx.x >> 5;
    const int qg = blk * 8 + w * 2;
    const int b = qg >= N;
    const int n0 = qg - (b ? N : 0);
    const int base = SOFFs[s] + (b ? N : 0);

    const float4* R = g_pp2 + base;
    const float4* W = g_pw + base;
    const float4 q0 = W[n0], q1 = W[n0 + 1];

    float d0[5], d1[5]; int i0[5], i1[5];
    initK<5>(d0, i0); initK<5>(d1, i1);
    scan2g<5>(R, N, lane, q0, q1, d0, i0, d1, i1);

    float lossw = 0.0f;
#pragma unroll
    for (int qq = 0; qq < 2; ++qq) {
        float sd; int si; float m0;
        if (qq == 0) mergeK<5>(lane, d0, i0, sd, si, m0);
        else         mergeK<5>(lane, d1, i1, sd, si, m0);
        const float4 q = (qq == 0) ? q0 : q1;
        const float qsq = q.w;
        const float dist1 = m0 + qsq;

        float wgt = 0.0f;
        float4 c = make_float4(0.f, 0.f, 0.f, 0.f);
        if (lane < 5) {
            wgt = 1.0f / ((sd + qsq) + 1e-8f);
            c = g_cv2[base + si];
        }
        float wsum = wsum32(wgt);
        float px = 0.f, py = 0.f, pz = 0.f;
        if (lane < 5) {
            float ww = wgt / wsum;
            px = ww * c.x; py = ww * c.y; pz = ww * c.z;
        }
        float ix = wsum32(px), iy = wsum32(py), iz = wsum32(pz);
        if (lane == 0) {
            float4 cw = g_cvw[base + n0 + qq];
            float ex = ix - cw.x, ey = iy - cw.y, ez = iz - cw.z;
            float curv = fmaf(ex, ex, fmaf(ey, ey, ez * ez));
            lossw += w_ch * dist1 + w_cv * curv;
        }
    }

    __shared__ float acc;
    if (threadIdx.x == 0) acc = 0.0f;
    __syncthreads();
    if (lane == 0) atomicAdd(&acc, lossw);
    __syncthreads();
    if (threadIdx.x == 0) atomicAdd(out, acc);
}

// ---------------------------------------------------------------------------

extern "C" void kernel_launch(void* const* d_in, const int* in_sizes, int n_in,
                              void* d_out, int out_size) {
    float* out = (float*)d_out;
    InPtrs in;
    for (int i = 0; i < 12; ++i) in.p[i] = (const float*)d_in[i];

    kPackAll<<<120, 256>>>(in, out);
    kABD<<<11520, TB>>>(out);
    kC<<<3840, TB>>>(out);
}

// round 4
// speedup vs baseline: 4.5036x; 1.3515x over previous
#include <cuda_runtime.h>
#include <math.h>
#include <float.h>

// ---------------------------------------------------------------------------
// PointPWC multi-scale loss — sorted-window exact kNN.
//
// Each cloud is sorted by x. A warp handles 2 adjacent sorted queries and
// expands a window outward in 32-point chunks. Top-K is a warp-distributed
// sorted list (entry r on lane r); the gate is the exact running Kth
// (true sqdist). A side stops exactly when its edge has (dx)^2 >= gate and
// the edge is on the receding side of the query.
// ---------------------------------------------------------------------------

#define TB 256
#define FULLM 0xffffffffu

// sorted packed arrays (x,y,z,|p|^2), per-scale offsets in points (B*N each)
__device__ float4 g_s1p[30720];   // p1 sorted by p1.x
__device__ float4 g_s1w[30720];   // warp, in p1.x-sorted order
__device__ float4 g_s2 [30720];   // p2 sorted by p2.x
__device__ float4 g_sw [30720];   // warp sorted by warp.x
__device__ float4 g_cv2[30720];   // indexed by s2 position
__device__ float4 g_cvw[30720];   // indexed by s1 position

struct InPtrs { const float* p[12]; };

__device__ __forceinline__ float wsum32(float v) {
#pragma unroll
    for (int o = 16; o; o >>= 1) v += __shfl_xor_sync(FULLM, v, o);
    return v;
}

// ---------------------------------------------------------------------------
// 32-ary search: last index with x <= qx (0 if none). Rx = float4 base as float*.
// ---------------------------------------------------------------------------
__device__ __forceinline__ int searchPos(const float* Rx, int N, float qx, int lane) {
    int base = 0, span = N;
    while (span > 32) {
        int step = span >> 5;
        int idx = base + lane * step;
        float v = __ldg(&Rx[4 * idx]);
        unsigned m = __ballot_sync(FULLM, v <= qx);
        int L = m ? (31 - __clz(m)) : 0;
        base += L * step;
        span = step;
    }
    int idx = base + lane;
    bool ok = (lane < span) && (idx < N) && (__ldg(&Rx[4 * idx]) <= qx);
    unsigned m = __ballot_sync(FULLM, ok);
    int off = m ? (31 - __clz(m)) : 0;
    return base + off;
}

// ---------------------------------------------------------------------------
// Window kNN for 2 queries. Returns: lane r holds the r-th nearest (true
// sqdist, sorted ascending) for each query (lanes >= K hold garbage).
// ---------------------------------------------------------------------------
template <int K>
__device__ __forceinline__ void windowKNN(
    const float4* __restrict__ R, int N, int lane,
    float4 q0, float4 q1, int start,
    float& od0, int& op0, float& od1, int& op1)
{
    const float a0 = -2.f * q0.x, b0 = -2.f * q0.y, c0 = -2.f * q0.z;
    const float a1 = -2.f * q1.x, b1 = -2.f * q1.y, c1 = -2.f * q1.z;
    const float* Rx = (const float*)R;

    int c = start - 15;
    if (c < 0) c = 0;
    if (c > N - 32) c = N - 32;
    int l = c - 1, r = c + 32;

    // ---- warm-up chunk (fully in range) ----
    int pos = c + lane;
    float4 rp = __ldg(&R[pos]);
    float t0 = fmaf(a0, rp.x, fmaf(b0, rp.y, fmaf(c0, rp.z, rp.w + q0.w)));
    float t1 = fmaf(a1, rp.x, fmaf(b1, rp.y, fmaf(c1, rp.z, rp.w + q1.w)));

    float ld0 = FLT_MAX, ld1 = FLT_MAX;
    int   lp0 = 0,       lp1 = 0;
    {   // q0 extraction
        float tt = t0; int pp = pos;
#pragma unroll
        for (int rr = 0; rr < K; ++rr) {
            float bd = tt; int bi = pp;
#pragma unroll
            for (int o = 16; o; o >>= 1) {
                float od = __shfl_xor_sync(FULLM, bd, o);
                int   oi = __shfl_xor_sync(FULLM, bi, o);
                if (od < bd || (od == bd && oi < bi)) { bd = od; bi = oi; }
            }
            if (lane == rr) { ld0 = bd; lp0 = bi; }
            if (tt == bd && pp == bi) tt = FLT_MAX;
        }
    }
    {   // q1 extraction
        float tt = t1; int pp = pos;
#pragma unroll
        for (int rr = 0; rr < K; ++rr) {
            float bd = tt; int bi = pp;
#pragma unroll
            for (int o = 16; o; o >>= 1) {
                float od = __shfl_xor_sync(FULLM, bd, o);
                int   oi = __shfl_xor_sync(FULLM, bi, o);
                if (od < bd || (od == bd && oi < bi)) { bd = od; bi = oi; }
            }
            if (lane == rr) { ld1 = bd; lp1 = bi; }
            if (tt == bd && pp == bi) tt = FLT_MAX;
        }
    }
    float g0 = __shfl_sync(FULLM, ld0, K - 1);
    float g1 = __shfl_sync(FULLM, ld1, K - 1);

    bool ldone = (l < 0), rdone = (r >= N);
    if (!ldone) {
        float xl = __ldg(&Rx[4 * l]);
        float dl0 = q0.x - xl, dl1 = q1.x - xl;
        ldone = (dl0 >= 0.f && dl0 * dl0 >= g0) && (dl1 >= 0.f && dl1 * dl1 >= g1);
    }
    if (!rdone) {
        float xr = __ldg(&Rx[4 * r]);
        float dr0 = xr - q0.x, dr1 = xr - q1.x;
        rdone = (dr0 >= 0.f && dr0 * dr0 >= g0) && (dr1 >= 0.f && dr1 * dr1 >= g1);
    }

    while (!(ldone && rdone)) {
        bool goLeft;
        if (ldone) goLeft = false;
        else if (rdone) goLeft = true;
        else {
            float xl = __ldg(&Rx[4 * l]);
            float xr = __ldg(&Rx[4 * r]);
            goLeft = fabsf(q0.x - xl) <= fabsf(xr - q0.x);
        }
        int pbase = goLeft ? (l - 31) : r;
        if (goLeft) l -= 32; else r += 32;

        int pos2 = pbase + lane;
        bool valid = (pos2 >= 0) && (pos2 < N);
        int pcl = valid ? pos2 : 0;
        float4 rq = __ldg(&R[pcl]);
        float u0 = fmaf(a0, rq.x, fmaf(b0, rq.y, fmaf(c0, rq.z, rq.w + q0.w)));
        float u1 = fmaf(a1, rq.x, fmaf(b1, rq.y, fmaf(c1, rq.z, rq.w + q1.w)));
        if (!valid) { u0 = FLT_MAX; u1 = FLT_MAX; }

        // event loop q0
        for (;;) {
            unsigned bal = __ballot_sync(FULLM, u0 < g0);
            if (!bal) break;
            int src = __ffs(bal) - 1;
            float bt = __shfl_sync(FULLM, u0, src);
            int   bp = __shfl_sync(FULLM, pos2, src);
            if (lane == src) u0 = FLT_MAX;
            bool ins = (lane < K) && (bt < ld0);
            unsigned im = __ballot_sync(FULLM, ins);
            float pd = __shfl_up_sync(FULLM, ld0, 1);
            int   pi = __shfl_up_sync(FULLM, lp0, 1);
            bool pins = (lane > 0) && ((im >> (lane - 1)) & 1u);
            if (ins) { ld0 = pins ? pd : bt; lp0 = pins ? pi : bp; }
            g0 = __shfl_sync(FULLM, ld0, K - 1);
        }
        // event loop q1
        for (;;) {
            unsigned bal = __ballot_sync(FULLM, u1 < g1);
            if (!bal) break;
            int src = __ffs(bal) - 1;
            float bt = __shfl_sync(FULLM, u1, src);
            int   bp = __shfl_sync(FULLM, pos2, src);
            if (lane == src) u1 = FLT_MAX;
            bool ins = (lane < K) && (bt < ld1);
            unsigned im = __ballot_sync(FULLM, ins);
            float pd = __shfl_up_sync(FULLM, ld1, 1);
            int   pi = __shfl_up_sync(FULLM, lp1, 1);
            bool pins = (lane > 0) && ((im >> (lane - 1)) & 1u);
            if (ins) { ld1 = pins ? pd : bt; lp1 = pins ? pi : bp; }
            g1 = __shfl_sync(FULLM, ld1, K - 1);
        }

        if (l < 0) ldone = true;
        else if (!ldone) {
            float xl = __ldg(&Rx[4 * l]);
            float dl0 = q0.x - xl, dl1 = q1.x - xl;
            ldone = (dl0 >= 0.f && dl0 * dl0 >= g0) && (dl1 >= 0.f && dl1 * dl1 >= g1);
        }
        if (r >= N) rdone = true;
        else if (!rdone) {
            float xr = __ldg(&Rx[4 * r]);
            float dr0 = xr - q0.x, dr1 = xr - q1.x;
            rdone = (dr0 >= 0.f && dr0 * dr0 >= g0) && (dr1 >= 0.f && dr1 * dr1 >= g1);
        }
    }
    od0 = ld0; op0 = lp0; od1 = ld1; op1 = lp1;
}

// ---------------------------------------------------------------------------
// Sort kernel: 24 blocks, one (scale,batch,array) bitonic sort each.
// arr 0: p1 (writes g_s1p + g_s1w), arr 1: p2 (g_s2), arr 2: warp (g_sw).
// ---------------------------------------------------------------------------
__global__ void __launch_bounds__(512)
kSort(InPtrs in, float* __restrict__ out) {
    extern __shared__ char sm[];
    float* skey = (float*)sm;
    unsigned short* sidx = (unsigned short*)(sm + 32768);

    const int NS[4]   = {8192, 4096, 2048, 1024};
    const int SOFF[4] = {0, 16384, 24576, 28672};
    int bid = blockIdx.x;
    if (bid == 0 && threadIdx.x == 0) out[0] = 0.0f;
    int s = bid / 6, rem = bid % 6, b = rem / 3, arr = rem % 3;
    const int N = NS[s];
    const float* P1 = in.p[s]     + (size_t)b * 3 * N;
    const float* P2 = in.p[4 + s] + (size_t)b * 3 * N;
    const float* F  = in.p[8 + s] + (size_t)b * 3 * N;

    for (int i = threadIdx.x; i < N; i += 512) {
        float x;
        if      (arr == 0) x = P1[i];
        else if (arr == 1) x = P2[i];
        else               x = P1[i] + F[i];
        skey[i] = x; sidx[i] = (unsigned short)i;
    }
    __syncthreads();

    for (int k = 2; k <= N; k <<= 1) {
        for (int j = k >> 1; j > 0; j >>= 1) {
            for (int i = threadIdx.x; i < N; i += 512) {
                int ixj = i ^ j;
                if (ixj > i) {
                    bool up = ((i & k) == 0);
                    float ki = skey[i], kj = skey[ixj];
                    bool sw = up ? (ki > kj) : (ki < kj);
                    if (sw) {
                        skey[i] = kj; skey[ixj] = ki;
                        unsigned short t = sidx[i]; sidx[i] = sidx[ixj]; sidx[ixj] = t;
                    }
                }
            }
            __syncthreads();
        }
    }

    int gbase = SOFF[s] + b * N;
    for (int i = threadIdx.x; i < N; i += 512) {
        int j = sidx[i];
        if (arr == 0) {
            float x = P1[j], y = P1[j + N], z = P1[j + 2 * N];
            g_s1p[gbase + i] = make_float4(x, y, z, fmaf(x, x, fmaf(y, y, z * z)));
            float wx = x + F[j], wy = y + F[j + N], wz = z + F[j + 2 * N];
            g_s1w[gbase + i] = make_float4(wx, wy, wz, fmaf(wx, wx, fmaf(wy, wy, wz * wz)));
        } else if (arr == 1) {
            float x = P2[j], y = P2[j + N], z = P2[j + 2 * N];
            g_s2[gbase + i] = make_float4(x, y, z, fmaf(x, x, fmaf(y, y, z * z)));
        } else {
            float x = P1[j] + F[j], y = P1[j + N] + F[j + N], z = P1[j + 2 * N] + F[j + 2 * N];
            g_sw[gbase + i] = make_float4(x, y, z, fmaf(x, x, fmaf(y, y, z * z)));
        }
    }
}

// ---------------------------------------------------------------------------
// Fused A/B/D: type 0 = cv2 (p2 self-kNN 10), type 1 = cvw + smooth (p1 self-
// kNN 10), type 2 = chamfer dist2 (p2 -> warp NN).
// ---------------------------------------------------------------------------
__global__ void __launch_bounds__(TB)
kABD(float* __restrict__ out) {
    const int   NS[4]   = {8192, 4096, 2048, 1024};
    const int   SOFF[4] = {0, 16384, 24576, 28672};
    const float AB[4]   = {0.01f, 0.02f, 0.04f, 0.08f};
    int bx = blockIdx.x;
    int s, rel;
    if      (bx < 3072) { s = 0; rel = bx; }
    else if (bx < 4608) { s = 1; rel = bx - 3072; }
    else if (bx < 5376) { s = 2; rel = bx - 4608; }
    else                { s = 3; rel = bx - 5376; }
    const int N = NS[s];
    const int perType = N >> 3;
    int type = rel / perType;
    int blk = rel - type * perType;

    int lane = threadIdx.x & 31, w = threadIdx.x >> 5;
    int qg = blk * 16 + w * 2;
    int b = (qg >= N);
    int n0 = qg - (b ? N : 0);
    int base = SOFF[s] + (b ? N : 0);

    __shared__ float acc;
    if (threadIdx.x == 0) acc = 0.0f;
    __syncthreads();
    float contrib = 0.0f;

    if (type == 0) {
        const float4* P = g_s2 + base;
        float4 q0 = P[n0], q1 = P[n0 + 1];
        float d0, d1; int p0, p1v;
        windowKNN<10>(P, N, lane, q0, q1, n0, d0, p0, d1, p1v);
#pragma unroll
        for (int qq = 0; qq < 2; ++qq) {
            int pp = qq ? p1v : p0;
            float sx = 0.f, sy = 0.f, sz = 0.f;
            if (lane < 10) { float4 nb = __ldg(&P[pp]); sx = nb.x; sy = nb.y; sz = nb.z; }
            sx = wsum32(sx); sy = wsum32(sy); sz = wsum32(sz);
            if (lane == 0) {
                float4 q = qq ? q1 : q0;
                const float inv9 = 1.0f / 9.0f;
                g_cv2[base + n0 + qq] = make_float4((sx - 10.0f * q.x) * inv9,
                                                    (sy - 10.0f * q.y) * inv9,
                                                    (sz - 10.0f * q.z) * inv9, 0.0f);
            }
        }
    } else if (type == 1) {
        const float4* P = g_s1p + base;
        const float4* W = g_s1w + base;
        float4 q0 = P[n0], q1 = P[n0 + 1];
        float d0, d1; int p0, p1v;
        windowKNN<10>(P, N, lane, q0, q1, n0, d0, p0, d1, p1v);
#pragma unroll
        for (int qq = 0; qq < 2; ++qq) {
            int pp = qq ? p1v : p0;
            const int n = n0 + qq;
            float4 qP = qq ? q1 : q0;
            float4 qW = __ldg(&W[n]);
            float flqx = qW.x - qP.x, flqy = qW.y - qP.y, flqz = qW.z - qP.z;
            float sx = 0.f, sy = 0.f, sz = 0.f, sm = 0.f;
            if (lane < 10) {
                float4 nw = __ldg(&W[pp]);
                sx = nw.x; sy = nw.y; sz = nw.z;
                if (lane < 9) {
                    float4 np = __ldg(&P[pp]);
                    float fx = (nw.x - np.x) - flqx;
                    float fy = (nw.y - np.y) - flqy;
                    float fz = (nw.z - np.z) - flqz;
                    sm = sqrtf(fmaf(fx, fx, fmaf(fy, fy, fz * fz)));
                }
            }
            sx = wsum32(sx); sy = wsum32(sy); sz = wsum32(sz); sm = wsum32(sm);
            if (lane == 0) {
                const float inv9 = 1.0f / 9.0f;
                g_cvw[base + n] = make_float4((sx - 10.0f * qW.x) * inv9,
                                              (sy - 10.0f * qW.y) * inv9,
                                              (sz - 10.0f * qW.z) * inv9, 0.0f);
                contrib += AB[s] * sm * 0.125f;
            }
        }
    } else {
        const float4* R = g_sw + base;
        const float4* Q = g_s2 + base;
        float4 q0 = Q[n0], q1 = Q[n0 + 1];
        int start = searchPos((const float*)R, N, q0.x, lane);
        float d0, d1; int p0, p1v;
        windowKNN<1>(R, N, lane, q0, q1, start, d0, p0, d1, p1v);
        float m0 = __shfl_sync(FULLM, d0, 0);
        float m1 = __shfl_sync(FULLM, d1, 0);
        if (lane == 0) contrib = AB[s] * (m0 + m1);
    }

    if (lane == 0 && contrib != 0.0f) atomicAdd(&acc, contrib);
    __syncthreads();
    if (threadIdx.x == 0 && acc != 0.0f) atomicAdd(out, acc);
}

// ---------------------------------------------------------------------------
// C: kNN(warp->p2, 5): chamfer dist1 + curvature.
// ---------------------------------------------------------------------------
__global__ void __launch_bounds__(TB)
kC(float* __restrict__ out) {
    const int   NS[4]   = {8192, 4096, 2048, 1024};
    const int   SOFF[4] = {0, 16384, 24576, 28672};
    const float AB[4]   = {0.01f, 0.02f, 0.04f, 0.08f};
    int bx = blockIdx.x;
    int s, blk;
    if      (bx < 1024) { s = 0; blk = bx; }
    else if (bx < 1536) { s = 1; blk = bx - 1024; }
    else if (bx < 1792) { s = 2; blk = bx - 1536; }
    else                { s = 3; blk = bx - 1792; }
    const int N = NS[s];
    const float w_ch = AB[s];
    const float w_cv = 0.3f * AB[s];

    int lane = threadIdx.x & 31, w = threadIdx.x >> 5;
    int qg = blk * 16 + w * 2;
    int b = (qg >= N);
    int n0 = qg - (b ? N : 0);
    int base = SOFF[s] + (b ? N : 0);

    const float4* R = g_s2 + base;     // refs: p2 sorted
    const float4* Wq = g_s1w + base;   // queries: warp in s1 order
    float4 q0 = Wq[n0], q1 = Wq[n0 + 1];
    int start = searchPos((const float*)R, N, q0.x, lane);

    float d0, d1; int p0, p1v;
    windowKNN<5>(R, N, lane, q0, q1, start, d0, p0, d1, p1v);

    float lossw = 0.0f;
#pragma unroll
    for (int qq = 0; qq < 2; ++qq) {
        float dd = qq ? d1 : d0;
        int pp = qq ? p1v : p0;
        float dist1 = __shfl_sync(FULLM, dd, 0);

        float wgt = 0.0f;
        float4 cc = make_float4(0.f, 0.f, 0.f, 0.f);
        if (lane < 5) {
            wgt = 1.0f / (dd + 1e-8f);
            cc = __ldg(&g_cv2[base + pp]);
        }
        float wsum = wsum32(wgt);
        float px = 0.f, py = 0.f, pz = 0.f;
        if (lane < 5) {
            float ww = wgt / wsum;
            px = ww * cc.x; py = ww * cc.y; pz = ww * cc.z;
        }
        float ix = wsum32(px), iy = wsum32(py), iz = wsum32(pz);
        if (lane == 0) {
            float4 cw = g_cvw[base + n0 + qq];
            float ex = ix - cw.x, ey = iy - cw.y, ez = iz - cw.z;
            float curv = fmaf(ex, ex, fmaf(ey, ey, ez * ez));
            lossw += w_ch * dist1 + w_cv * curv;
        }
    }

    __shared__ float acc;
    if (threadIdx.x == 0) acc = 0.0f;
    __syncthreads();
    if (lane == 0) atomicAdd(&acc, lossw);
    __syncthreads();
    if (threadIdx.x == 0) atomicAdd(out, acc);
}

// ---------------------------------------------------------------------------

extern "C" void kernel_launch(void* const* d_in, const int* in_sizes, int n_in,
                              void* d_out, int out_size) {
    float* out = (float*)d_out;
    InPtrs in;
    for (int i = 0; i < 12; ++i) in.p[i] = (const float*)d_in[i];

    kSort<<<24, 512, 49152>>>(in, out);   // 32KB keys + 16KB idx = 48KB smem
    kABD<<<5760, TB>>>(out);
    kC<<<1920, TB>>>(out);
}

// round 5
// speedup vs baseline: 6.3839x; 1.4175x over previous
#include <cuda_runtime.h>
#include <math.h>
#include <float.h>

// ---------------------------------------------------------------------------
// PointPWC multi-scale loss — bin-sorted-window exact kNN.
//
// Counting sort by x into 512 bins (exact within one bin width). A warp
// handles 2 adjacent queries, expanding a window outward in 32-point chunks
// with an exact stop rule relaxed by one bin width BW:
//   points beyond the left edge l have x <= x_l + BW, so
//   (qx - x_l - BW) >= 0 and (qx - x_l - BW)^2 >= Kth  => provably done.
// ---------------------------------------------------------------------------

#define TB 256
#define FULLM 0xffffffffu
#define NB 512
#define XLO (-6.0f)
#define XSCALE (512.0f / 12.0f)
#define BW 0.0234375f

// bin-sorted packed arrays (x,y,z,|p|^2); per-scale offsets in points
__device__ float4 g_s1p[30720];   // p1 sorted by p1.x
__device__ float4 g_s1w[30720];   // warp, in p1.x-sorted order
__device__ float4 g_s2 [30720];   // p2 sorted by p2.x
__device__ float4 g_sw [30720];   // warp sorted by warp.x
__device__ float4 g_cv2[30720];   // indexed by s2 position
__device__ float4 g_cvw[30720];   // indexed by s1 position
__device__ int    g_hist[24 * NB];

struct InPtrs { const float* p[12]; };

__device__ __forceinline__ float wsum32(float v) {
#pragma unroll
    for (int o = 16; o; o >>= 1) v += __shfl_xor_sync(FULLM, v, o);
    return v;
}

__device__ __forceinline__ void decodeLoc(int loc, int& s, int& N, int& b, int& n) {
    const int NS[4] = {8192, 4096, 2048, 1024};
    int l;
    if      (loc < 16384) { s = 0; l = loc; }
    else if (loc < 24576) { s = 1; l = loc - 16384; }
    else if (loc < 28672) { s = 2; l = loc - 24576; }
    else                  { s = 3; l = loc - 28672; }
    N = NS[s];
    b = l >= N;
    n = l - (b ? N : 0);
}

// ---------------------------------------------------------------------------
// Counting sort pipeline
// ---------------------------------------------------------------------------
__global__ void __launch_bounds__(256)
kInit(float* __restrict__ out) {
    int i = blockIdx.x * 256 + threadIdx.x;
    if (i == 0) out[0] = 0.0f;
    if (i < 24 * NB) g_hist[i] = 0;
}

__global__ void __launch_bounds__(256)
kHist(InPtrs in) {
    int idx = blockIdx.x * 256 + threadIdx.x;
    if (idx >= 3 * 30720) return;
    int arr = idx / 30720, loc = idx - arr * 30720;
    int s, N, b, n;
    decodeLoc(loc, s, N, b, n);
    size_t off = (size_t)b * 3 * N;
    float x;
    if      (arr == 0) x = in.p[s][off + n];
    else if (arr == 1) x = in.p[4 + s][off + n];
    else               x = in.p[s][off + n] + in.p[8 + s][off + n];
    int bin = (int)((x - XLO) * XSCALE);
    bin = min(NB - 1, max(0, bin));
    int g = (s * 2 + b) * 3 + arr;
    atomicAdd(&g_hist[g * NB + bin], 1);
}

__global__ void __launch_bounds__(NB)
kScan() {
    __shared__ int sh[NB];
    int g = blockIdx.x, t = threadIdx.x;
    int cnt = g_hist[g * NB + t];
    sh[t] = cnt;
    __syncthreads();
#pragma unroll
    for (int off = 1; off < NB; off <<= 1) {
        int v = (t >= off) ? sh[t - off] : 0;
        __syncthreads();
        sh[t] += v;
        __syncthreads();
    }
    g_hist[g * NB + t] = sh[t] - cnt;   // exclusive prefix = scatter counter base
}

__global__ void __launch_bounds__(256)
kScatter(InPtrs in) {
    int idx = blockIdx.x * 256 + threadIdx.x;
    if (idx >= 3 * 30720) return;
    int arr = idx / 30720, loc = idx - arr * 30720;
    int s, N, b, n;
    decodeLoc(loc, s, N, b, n);
    const int SOFF[4] = {0, 16384, 24576, 28672};
    size_t off = (size_t)b * 3 * N;
    const float* P1 = in.p[s]     + off;
    const float* P2 = in.p[4 + s] + off;
    const float* F  = in.p[8 + s] + off;

    float x, y, z;
    if (arr == 0)      { x = P1[n]; y = P1[n + N]; z = P1[n + 2 * N]; }
    else if (arr == 1) { x = P2[n]; y = P2[n + N]; z = P2[n + 2 * N]; }
    else { x = P1[n] + F[n]; y = P1[n + N] + F[n + N]; z = P1[n + 2 * N] + F[n + 2 * N]; }

    int bin = (int)((x - XLO) * XSCALE);
    bin = min(NB - 1, max(0, bin));
    int g = (s * 2 + b) * 3 + arr;
    int pos = atomicAdd(&g_hist[g * NB + bin], 1);
    int gdst = SOFF[s] + b * N + pos;

    if (arr == 0) {
        g_s1p[gdst] = make_float4(x, y, z, fmaf(x, x, fmaf(y, y, z * z)));
        float wx = x + F[n], wy = y + F[n + N], wz = z + F[n + 2 * N];
        g_s1w[gdst] = make_float4(wx, wy, wz, fmaf(wx, wx, fmaf(wy, wy, wz * wz)));
    } else if (arr == 1) {
        g_s2[gdst] = make_float4(x, y, z, fmaf(x, x, fmaf(y, y, z * z)));
    } else {
        g_sw[gdst] = make_float4(x, y, z, fmaf(x, x, fmaf(y, y, z * z)));
    }
}

// ---------------------------------------------------------------------------
// 32-ary search: approx last index with x <= qx (exact up to bin locality,
// which only affects the starting point, not correctness).
// ---------------------------------------------------------------------------
__device__ __forceinline__ int searchPos(const float* Rx, int N, float qx, int lane) {
    int base = 0, span = N;
    while (span > 32) {
        int step = span >> 5;
        int idx = base + lane * step;
        float v = __ldg(&Rx[4 * idx]);
        unsigned m = __ballot_sync(FULLM, v <= qx);
        int L = m ? (31 - __clz(m)) : 0;
        base += L * step;
        span = step;
    }
    int idx = base + lane;
    bool ok = (lane < span) && (idx < N) && (__ldg(&Rx[4 * idx]) <= qx);
    unsigned m = __ballot_sync(FULLM, ok);
    int off = m ? (31 - __clz(m)) : 0;
    return base + off;
}

// ---------------------------------------------------------------------------
// Window kNN for 2 queries over a bin-sorted array. Lane r ends with the
// r-th nearest (true sqdist, ascending) for each query.
// ---------------------------------------------------------------------------
template <int K>
__device__ __forceinline__ void windowKNN(
    const float4* __restrict__ R, int N, int lane,
    float4 q0, float4 q1, int start,
    float& od0, int& op0, float& od1, int& op1)
{
    const float a0 = -2.f * q0.x, b0 = -2.f * q0.y, c0 = -2.f * q0.z;
    const float a1 = -2.f * q1.x, b1 = -2.f * q1.y, c1 = -2.f * q1.z;
    const float* Rx = (const float*)R;

    int c = start - 15;
    if (c < 0) c = 0;
    if (c > N - 32) c = N - 32;
    int l = c - 1, r = c + 32;

    // ---- warm-up chunk ----
    int pos = c + lane;
    float4 rp = __ldg(&R[pos]);
    float t0 = fmaf(a0, rp.x, fmaf(b0, rp.y, fmaf(c0, rp.z, rp.w + q0.w)));
    float t1 = fmaf(a1, rp.x, fmaf(b1, rp.y, fmaf(c1, rp.z, rp.w + q1.w)));

    float ld0 = FLT_MAX, ld1 = FLT_MAX;
    int   lp0 = 0,       lp1 = 0;
    {
        float tt = t0; int pp = pos;
#pragma unroll
        for (int rr = 0; rr < K; ++rr) {
            float bd = tt; int bi = pp;
#pragma unroll
            for (int o = 16; o; o >>= 1) {
                float od = __shfl_xor_sync(FULLM, bd, o);
                int   oi = __shfl_xor_sync(FULLM, bi, o);
                if (od < bd || (od == bd && oi < bi)) { bd = od; bi = oi; }
            }
            if (lane == rr) { ld0 = bd; lp0 = bi; }
            if (tt == bd && pp == bi) tt = FLT_MAX;
        }
    }
    {
        float tt = t1; int pp = pos;
#pragma unroll
        for (int rr = 0; rr < K; ++rr) {
            float bd = tt; int bi = pp;
#pragma unroll
            for (int o = 16; o; o >>= 1) {
                float od = __shfl_xor_sync(FULLM, bd, o);
                int   oi = __shfl_xor_sync(FULLM, bi, o);
                if (od < bd || (od == bd && oi < bi)) { bd = od; bi = oi; }
            }
            if (lane == rr) { ld1 = bd; lp1 = bi; }
            if (tt == bd && pp == bi) tt = FLT_MAX;
        }
    }
    float g0 = __shfl_sync(FULLM, ld0, K - 1);
    float g1 = __shfl_sync(FULLM, ld1, K - 1);

    bool ldone = (l < 0), rdone = (r >= N);
    if (!ldone) {
        float xl = __ldg(&Rx[4 * l]);
        float dl0 = q0.x - xl - BW, dl1 = q1.x - xl - BW;
        ldone = (dl0 >= 0.f && dl0 * dl0 >= g0) && (dl1 >= 0.f && dl1 * dl1 >= g1);
    }
    if (!rdone) {
        float xr = __ldg(&Rx[4 * r]);
        float dr0 = xr - q0.x - BW, dr1 = xr - q1.x - BW;
        rdone = (dr0 >= 0.f && dr0 * dr0 >= g0) && (dr1 >= 0.f && dr1 * dr1 >= g1);
    }

    while (!(ldone && rdone)) {
        bool goLeft;
        if (ldone) goLeft = false;
        else if (rdone) goLeft = true;
        else {
            float xl = __ldg(&Rx[4 * l]);
            float xr = __ldg(&Rx[4 * r]);
            goLeft = fabsf(q0.x - xl) <= fabsf(xr - q0.x);
        }
        int pbase = goLeft ? (l - 31) : r;
        if (goLeft) l -= 32; else r += 32;

        int pos2 = pbase + lane;
        bool valid = (pos2 >= 0) && (pos2 < N);
        int pcl = valid ? pos2 : 0;
        float4 rq = __ldg(&R[pcl]);
        float u0 = fmaf(a0, rq.x, fmaf(b0, rq.y, fmaf(c0, rq.z, rq.w + q0.w)));
        float u1 = fmaf(a1, rq.x, fmaf(b1, rq.y, fmaf(c1, rq.z, rq.w + q1.w)));
        if (!valid) { u0 = FLT_MAX; u1 = FLT_MAX; }

        for (;;) {  // event loop q0
            unsigned bal = __ballot_sync(FULLM, u0 < g0);
            if (!bal) break;
            int src = __ffs(bal) - 1;
            float bt = __shfl_sync(FULLM, u0, src);
            int   bp = __shfl_sync(FULLM, pos2, src);
            if (lane == src) u0 = FLT_MAX;
            bool ins = (lane < K) && (bt < ld0);
            unsigned im = __ballot_sync(FULLM, ins);
            float pd = __shfl_up_sync(FULLM, ld0, 1);
            int   pi = __shfl_up_sync(FULLM, lp0, 1);
            bool pins = (lane > 0) && ((im >> (lane - 1)) & 1u);
            if (ins) { ld0 = pins ? pd : bt; lp0 = pins ? pi : bp; }
            g0 = __shfl_sync(FULLM, ld0, K - 1);
        }
        for (;;) {  // event loop q1
            unsigned bal = __ballot_sync(FULLM, u1 < g1);
            if (!bal) break;
            int src = __ffs(bal) - 1;
            float bt = __shfl_sync(FULLM, u1, src);
            int   bp = __shfl_sync(FULLM, pos2, src);
            if (lane == src) u1 = FLT_MAX;
            bool ins = (lane < K) && (bt < ld1);
            unsigned im = __ballot_sync(FULLM, ins);
            float pd = __shfl_up_sync(FULLM, ld1, 1);
            int   pi = __shfl_up_sync(FULLM, lp1, 1);
            bool pins = (lane > 0) && ((im >> (lane - 1)) & 1u);
            if (ins) { ld1 = pins ? pd : bt; lp1 = pins ? pi : bp; }
            g1 = __shfl_sync(FULLM, ld1, K - 1);
        }

        if (l < 0) ldone = true;
        else if (!ldone) {
            float xl = __ldg(&Rx[4 * l]);
            float dl0 = q0.x - xl - BW, dl1 = q1.x - xl - BW;
            ldone = (dl0 >= 0.f && dl0 * dl0 >= g0) && (dl1 >= 0.f && dl1 * dl1 >= g1);
        }
        if (r >= N) rdone = true;
        else if (!rdone) {
            float xr = __ldg(&Rx[4 * r]);
            float dr0 = xr - q0.x - BW, dr1 = xr - q1.x - BW;
            rdone = (dr0 >= 0.f && dr0 * dr0 >= g0) && (dr1 >= 0.f && dr1 * dr1 >= g1);
        }
    }
    od0 = ld0; op0 = lp0; od1 = ld1; op1 = lp1;
}

// ---------------------------------------------------------------------------
// Fused A/B/D
// ---------------------------------------------------------------------------
__global__ void __launch_bounds__(TB)
kABD(float* __restrict__ out) {
    const int   NS[4]   = {8192, 4096, 2048, 1024};
    const int   SOFF[4] = {0, 16384, 24576, 28672};
    const float AB[4]   = {0.01f, 0.02f, 0.04f, 0.08f};
    int bx = blockIdx.x;
    int s, rel;
    if      (bx < 3072) { s = 0; rel = bx; }
    else if (bx < 4608) { s = 1; rel = bx - 3072; }
    else if (bx < 5376) { s = 2; rel = bx - 4608; }
    else                { s = 3; rel = bx - 5376; }
    const int N = NS[s];
    const int perType = N >> 3;
    int type = rel / perType;
    int blk = rel - type * perType;

    int lane = threadIdx.x & 31, w = threadIdx.x >> 5;
    int qg = blk * 16 + w * 2;
    int b = (qg >= N);
    int n0 = qg - (b ? N : 0);
    int base = SOFF[s] + (b ? N : 0);

    __shared__ float acc;
    if (threadIdx.x == 0) acc = 0.0f;
    __syncthreads();
    float contrib = 0.0f;

    if (type == 0) {
        const float4* P = g_s2 + base;
        float4 q0 = P[n0], q1 = P[n0 + 1];
        float d0, d1; int p0, p1v;
        windowKNN<10>(P, N, lane, q0, q1, n0, d0, p0, d1, p1v);
#pragma unroll
        for (int qq = 0; qq < 2; ++qq) {
            int pp = qq ? p1v : p0;
            float sx = 0.f, sy = 0.f, sz = 0.f;
            if (lane < 10) { float4 nb = __ldg(&P[pp]); sx = nb.x; sy = nb.y; sz = nb.z; }
            sx = wsum32(sx); sy = wsum32(sy); sz = wsum32(sz);
            if (lane == 0) {
                float4 q = qq ? q1 : q0;
                const float inv9 = 1.0f / 9.0f;
                g_cv2[base + n0 + qq] = make_float4((sx - 10.0f * q.x) * inv9,
                                                    (sy - 10.0f * q.y) * inv9,
                                                    (sz - 10.0f * q.z) * inv9, 0.0f);
            }
        }
    } else if (type == 1) {
        const float4* P = g_s1p + base;
        const float4* W = g_s1w + base;
        float4 q0 = P[n0], q1 = P[n0 + 1];
        float d0, d1; int p0, p1v;
        windowKNN<10>(P, N, lane, q0, q1, n0, d0, p0, d1, p1v);
#pragma unroll
        for (int qq = 0; qq < 2; ++qq) {
            int pp = qq ? p1v : p0;
            const int n = n0 + qq;
            float4 qP = qq ? q1 : q0;
            float4 qW = __ldg(&W[n]);
            float flqx = qW.x - qP.x, flqy = qW.y - qP.y, flqz = qW.z - qP.z;
            float sx = 0.f, sy = 0.f, sz = 0.f, sm = 0.f;
            if (lane < 10) {
                float4 nw = __ldg(&W[pp]);
                sx = nw.x; sy = nw.y; sz = nw.z;
                if (lane < 9) {
                    float4 np = __ldg(&P[pp]);
                    float fx = (nw.x - np.x) - flqx;
                    float fy = (nw.y - np.y) - flqy;
                    float fz = (nw.z - np.z) - flqz;
                    sm = sqrtf(fmaf(fx, fx, fmaf(fy, fy, fz * fz)));
                }
            }
            sx = wsum32(sx); sy = wsum32(sy); sz = wsum32(sz); sm = wsum32(sm);
            if (lane == 0) {
                const float inv9 = 1.0f / 9.0f;
                g_cvw[base + n] = make_float4((sx - 10.0f * qW.x) * inv9,
                                              (sy - 10.0f * qW.y) * inv9,
                                              (sz - 10.0f * qW.z) * inv9, 0.0f);
                contrib += AB[s] * sm * 0.125f;
            }
        }
    } else {
        const float4* R = g_sw + base;
        const float4* Q = g_s2 + base;
        float4 q0 = Q[n0], q1 = Q[n0 + 1];
        int start = searchPos((const float*)R, N, q0.x, lane);
        float d0, d1; int p0, p1v;
        windowKNN<1>(R, N, lane, q0, q1, start, d0, p0, d1, p1v);
        float m0 = __shfl_sync(FULLM, d0, 0);
        float m1 = __shfl_sync(FULLM, d1, 0);
        if (lane == 0) contrib = AB[s] * (m0 + m1);
    }

    if (lane == 0 && contrib != 0.0f) atomicAdd(&acc, contrib);
    __syncthreads();
    if (threadIdx.x == 0 && acc != 0.0f) atomicAdd(out, acc);
}

// ---------------------------------------------------------------------------
// C: kNN(warp->p2, 5): chamfer dist1 + curvature.
// ---------------------------------------------------------------------------
__global__ void __launch_bounds__(TB)
kC(float* __restrict__ out) {
    const int   NS[4]   = {8192, 4096, 2048, 1024};
    const int   SOFF[4] = {0, 16384, 24576, 28672};
    const float AB[4]   = {0.01f, 0.02f, 0.04f, 0.08f};
    int bx = blockIdx.x;
    int s, blk;
    if      (bx < 1024) { s = 0; blk = bx; }
    else if (bx < 1536) { s = 1; blk = bx - 1024; }
    else if (bx < 1792) { s = 2; blk = bx - 1536; }
    else                { s = 3; blk = bx - 1792; }
    const int N = NS[s];
    const float w_ch = AB[s];
    const float w_cv = 0.3f * AB[s];

    int lane = threadIdx.x & 31, w = threadIdx.x >> 5;
    int qg = blk * 16 + w * 2;
    int b = (qg >= N);
    int n0 = qg - (b ? N : 0);
    int base = SOFF[s] + (b ? N : 0);

    const float4* R = g_s2 + base;
    const float4* Wq = g_s1w + base;
    float4 q0 = Wq[n0], q1 = Wq[n0 + 1];
    int start = searchPos((const float*)R, N, q0.x, lane);

    float d0, d1; int p0, p1v;
    windowKNN<5>(R, N, lane, q0, q1, start, d0, p0, d1, p1v);

    float lossw = 0.0f;
#pragma unroll
    for (int qq = 0; qq < 2; ++qq) {
        float dd = qq ? d1 : d0;
        int pp = qq ? p1v : p0;
        float dist1 = __shfl_sync(FULLM, dd, 0);

        float wgt = 0.0f;
        float4 cc = make_float4(0.f, 0.f, 0.f, 0.f);
        if (lane < 5) {
            wgt = 1.0f / (dd + 1e-8f);
            cc = __ldg(&g_cv2[base + pp]);
        }
        float wsum = wsum32(wgt);
        float px = 0.f, py = 0.f, pz = 0.f;
        if (lane < 5) {
            float ww = wgt / wsum;
            px = ww * cc.x; py = ww * cc.y; pz = ww * cc.z;
        }
        float ix = wsum32(px), iy = wsum32(py), iz = wsum32(pz);
        if (lane == 0) {
            float4 cw = g_cvw[base + n0 + qq];
            float ex = ix - cw.x, ey = iy - cw.y, ez = iz - cw.z;
            float curv = fmaf(ex, ex, fmaf(ey, ey, ez * ez));
            lossw += w_ch * dist1 + w_cv * curv;
        }
    }

    __shared__ float acc;
    if (threadIdx.x == 0) acc = 0.0f;
    __syncthreads();
    if (lane == 0) atomicAdd(&acc, lossw);
    __syncthreads();
    if (threadIdx.x == 0) atomicAdd(out, acc);
}

// ---------------------------------------------------------------------------

extern "C" void kernel_launch(void* const* d_in, const int* in_sizes, int n_in,
                              void* d_out, int out_size) {
    float* out = (float*)d_out;
    InPtrs in;
    for (int i = 0; i < 12; ++i) in.p[i] = (const float*)d_in[i];

    kInit<<<48, 256>>>(out);
    kHist<<<360, 256>>>(in);
    kScan<<<24, NB>>>();
    kScatter<<<360, 256>>>(in);
    kABD<<<5760, TB>>>(out);
    kC<<<1920, TB>>>(out);
}

// round 6
// speedup vs baseline: 7.9653x; 1.2477x over previous
#include <cuda_runtime.h>
#include <math.h>
#include <float.h>

// ---------------------------------------------------------------------------
// PointPWC multi-scale loss — bin-sorted-window exact kNN, proxy-edge version.
//
// Counting sort by x into 1024 bins. Bin-sorted => for i < j: x_i <= x_j + BW.
// So lane-0 (left) / lane-31 (right) x of the most recently loaded chunk is a
// valid edge bound with one BW of slack; no scalar edge loads needed.
// ---------------------------------------------------------------------------

#define TB 256
#define FULLM 0xffffffffu
#define NB 1024
#define XLO (-6.0f)
#define XSCALE (1024.0f / 12.0f)
#define BW 0.01171875f

__device__ float4 g_s1p[30720];   // p1 sorted by p1.x
__device__ float4 g_s1w[30720];   // warp, in p1.x-sorted order
__device__ float4 g_s2 [30720];   // p2 sorted by p2.x
__device__ float4 g_sw [30720];   // warp sorted by warp.x
__device__ float4 g_cv2[30720];
__device__ float4 g_cvw[30720];

struct InPtrs { const float* p[12]; };

__device__ __forceinline__ float wsum32(float v) {
#pragma unroll
    for (int o = 16; o; o >>= 1) v += __shfl_xor_sync(FULLM, v, o);
    return v;
}

// ---------------------------------------------------------------------------
// One-kernel counting sort: 24 blocks, one (scale,batch,array) group each.
// ---------------------------------------------------------------------------
__global__ void __launch_bounds__(NB)
kSortAll(InPtrs in, float* __restrict__ out) {
    __shared__ int hist[NB];
    const int NS[4]   = {8192, 4096, 2048, 1024};
    const int SOFF[4] = {0, 16384, 24576, 28672};
    int g = blockIdx.x;
    if (g == 0 && threadIdx.x == 0) out[0] = 0.0f;
    int s = g / 6, rem = g % 6, b = rem / 3, arr = rem % 3;
    const int N = NS[s];
    const float* P1 = in.p[s]     + (size_t)b * 3 * N;
    const float* P2 = in.p[4 + s] + (size_t)b * 3 * N;
    const float* F  = in.p[8 + s] + (size_t)b * 3 * N;
    const int t = threadIdx.x;

    hist[t] = 0;
    __syncthreads();

    for (int i = t; i < N; i += NB) {
        float x;
        if      (arr == 0) x = P1[i];
        else if (arr == 1) x = P2[i];
        else               x = P1[i] + F[i];
        int bin = (int)((x - XLO) * XSCALE);
        bin = min(NB - 1, max(0, bin));
        atomicAdd(&hist[bin], 1);
    }
    __syncthreads();

    // inclusive Hillis-Steele scan, then convert to exclusive
    int cnt = hist[t];
#pragma unroll
    for (int off = 1; off < NB; off <<= 1) {
        int w = (t >= off) ? hist[t - off] : 0;
        __syncthreads();
        hist[t] += w;
        __syncthreads();
    }
    int excl = hist[t] - cnt;
    __syncthreads();
    hist[t] = excl;
    __syncthreads();

    int gbase = SOFF[s] + b * N;
    for (int i = t; i < N; i += NB) {
        float x, y, z;
        if (arr == 0)      { x = P1[i]; y = P1[i + N]; z = P1[i + 2 * N]; }
        else if (arr == 1) { x = P2[i]; y = P2[i + N]; z = P2[i + 2 * N]; }
        else { x = P1[i] + F[i]; y = P1[i + N] + F[i + N]; z = P1[i + 2 * N] + F[i + 2 * N]; }
        int bin = (int)((x - XLO) * XSCALE);
        bin = min(NB - 1, max(0, bin));
        int pos = atomicAdd(&hist[bin], 1);
        int dst = gbase + pos;
        if (arr == 0) {
            g_s1p[dst] = make_float4(x, y, z, fmaf(x, x, fmaf(y, y, z * z)));
            float wx = x + F[i], wy = y + F[i + N], wz = z + F[i + 2 * N];
            g_s1w[dst] = make_float4(wx, wy, wz, fmaf(wx, wx, fmaf(wy, wy, wz * wz)));
        } else if (arr == 1) {
            g_s2[dst] = make_float4(x, y, z, fmaf(x, x, fmaf(y, y, z * z)));
        } else {
            g_sw[dst] = make_float4(x, y, z, fmaf(x, x, fmaf(y, y, z * z)));
        }
    }
}

// ---------------------------------------------------------------------------
// 32-ary search: approx last index with x <= qx (starting point only).
// ---------------------------------------------------------------------------
__device__ __forceinline__ int searchPos(const float* Rx, int N, float qx, int lane) {
    int base = 0, span = N;
    while (span > 32) {
        int step = span >> 5;
        int idx = base + lane * step;
        float v = __ldg(&Rx[4 * idx]);
        unsigned m = __ballot_sync(FULLM, v <= qx);
        int L = m ? (31 - __clz(m)) : 0;
        base += L * step;
        span = step;
    }
    int idx = base + lane;
    bool ok = (lane < span) && (idx < N) && (__ldg(&Rx[4 * idx]) <= qx);
    unsigned m = __ballot_sync(FULLM, ok);
    int off = m ? (31 - __clz(m)) : 0;
    return base + off;
}

// One insert-event pass over per-lane candidate register u (positions pp).
template <int K>
__device__ __forceinline__ void eventLoop(int lane, float& u, int pp,
                                          float& ld, int& lp, float& g) {
    for (;;) {
        unsigned bal = __ballot_sync(FULLM, u < g);
        if (!bal) break;
        int src = __ffs(bal) - 1;
        float bt = __shfl_sync(FULLM, u, src);
        int   bp = __shfl_sync(FULLM, pp, src);
        if (lane == src) u = FLT_MAX;
        bool ins = (lane < K) && (bt < ld);
        unsigned im = __ballot_sync(FULLM, ins);
        float pd = __shfl_up_sync(FULLM, ld, 1);
        int   pi = __shfl_up_sync(FULLM, lp, 1);
        bool pins = (lane > 0) && ((im >> (lane - 1)) & 1u);
        if (ins) { ld = pins ? pd : bt; lp = pins ? pi : bp; }
        g = __shfl_sync(FULLM, ld, K - 1);
    }
}

// ---------------------------------------------------------------------------
// Window kNN for 2 queries, proxy edges, 64-point expansion chunks.
// Lane r ends with the r-th nearest (true sqdist, ascending) for each query.
// ---------------------------------------------------------------------------
template <int K>
__device__ __forceinline__ void windowKNN(
    const float4* __restrict__ R, int N, int lane,
    float4 q0, float4 q1, int start,
    float& od0, int& op0, float& od1, int& op1)
{
    const float a0 = -2.f * q0.x, b0 = -2.f * q0.y, c0 = -2.f * q0.z;
    const float a1 = -2.f * q1.x, b1 = -2.f * q1.y, c1 = -2.f * q1.z;

    int c = start - 15;
    if (c < 0) c = 0;
    if (c > N - 32) c = N - 32;

    // ---- warm-up chunk (32, fully in range) ----
    int pos = c + lane;
    float4 rp = __ldg(&R[pos]);
    float t0 = fmaf(a0, rp.x, fmaf(b0, rp.y, fmaf(c0, rp.z, rp.w + q0.w)));
    float t1 = fmaf(a1, rp.x, fmaf(b1, rp.y, fmaf(c1, rp.z, rp.w + q1.w)));
    float xL = __shfl_sync(FULLM, rp.x, 0);
    float xR = __shfl_sync(FULLM, rp.x, 31);

    float ld0 = FLT_MAX, ld1 = FLT_MAX;
    int   lp0 = 0,       lp1 = 0;
    {
        float tt = t0; int pp = pos;
#pragma unroll
        for (int rr = 0; rr < K; ++rr) {
            float bd = tt; int bi = pp;
#pragma unroll
            for (int o = 16; o; o >>= 1) {
                float od = __shfl_xor_sync(FULLM, bd, o);
                int   oi = __shfl_xor_sync(FULLM, bi, o);
                if (od < bd || (od == bd && oi < bi)) { bd = od; bi = oi; }
            }
            if (lane == rr) { ld0 = bd; lp0 = bi; }
            if (tt == bd && pp == bi) tt = FLT_MAX;
        }
    }
    {
        float tt = t1; int pp = pos;
#pragma unroll
        for (int rr = 0; rr < K; ++rr) {
            float bd = tt; int bi = pp;
#pragma unroll
            for (int o = 16; o; o >>= 1) {
                float od = __shfl_xor_sync(FULLM, bd, o);
                int   oi = __shfl_xor_sync(FULLM, bi, o);
                if (od < bd || (od == bd && oi < bi)) { bd = od; bi = oi; }
            }
            if (lane == rr) { ld1 = bd; lp1 = bi; }
            if (tt == bd && pp == bi) tt = FLT_MAX;
        }
    }
    float g0 = __shfl_sync(FULLM, ld0, K - 1);
    float g1 = __shfl_sync(FULLM, ld1, K - 1);

    int l = c - 1, r = c + 32;
    bool ldone = (l < 0), rdone = (r >= N);

    for (;;) {
        if (!ldone) {
            float dl0 = q0.x - xL - BW, dl1 = q1.x - xL - BW;
            ldone = (l < 0) || ((dl0 >= 0.f) & (dl0 * dl0 >= g0) &
                                (dl1 >= 0.f) & (dl1 * dl1 >= g1));
        }
        if (!rdone) {
            float dr0 = xR - BW - q0.x, dr1 = xR - BW - q1.x;
            rdone = (r >= N) || ((dr0 >= 0.f) & (dr0 * dr0 >= g0) &
                                 (dr1 >= 0.f) & (dr1 * dr1 >= g1));
        }
        if (ldone && rdone) break;

        bool goLeft = !ldone && (rdone || (q0.x - xL) <= (xR - q0.x));
        int pbase;
        if (goLeft) { pbase = l - 63; l -= 64; }
        else        { pbase = r;      r += 64; }

        int pa = pbase + lane, pb = pbase + 32 + lane;
        bool va = (pa >= 0) & (pa < N);
        bool vb = (pb >= 0) & (pb < N);
        float4 ra = __ldg(&R[va ? pa : 0]);
        float4 rb = __ldg(&R[vb ? pb : 0]);
        if (goLeft) xL = __shfl_sync(FULLM, ra.x, 0);
        else        xR = __shfl_sync(FULLM, rb.x, 31);

        float u0a = fmaf(a0, ra.x, fmaf(b0, ra.y, fmaf(c0, ra.z, ra.w + q0.w)));
        float u1a = fmaf(a1, ra.x, fmaf(b1, ra.y, fmaf(c1, ra.z, ra.w + q1.w)));
        float u0b = fmaf(a0, rb.x, fmaf(b0, rb.y, fmaf(c0, rb.z, rb.w + q0.w)));
        float u1b = fmaf(a1, rb.x, fmaf(b1, rb.y, fmaf(c1, rb.z, rb.w + q1.w)));
        if (!va) { u0a = FLT_MAX; u1a = FLT_MAX; }
        if (!vb) { u0b = FLT_MAX; u1b = FLT_MAX; }

        eventLoop<K>(lane, u0a, pa, ld0, lp0, g0);
        eventLoop<K>(lane, u0b, pb, ld0, lp0, g0);
        eventLoop<K>(lane, u1a, pa, ld1, lp1, g1);
        eventLoop<K>(lane, u1b, pb, ld1, lp1, g1);
    }
    od0 = ld0; op0 = lp0; od1 = ld1; op1 = lp1;
}

// ---------------------------------------------------------------------------
// Fused A/B/D
// ---------------------------------------------------------------------------
__global__ void __launch_bounds__(TB)
kABD(float* __restrict__ out) {
    const int   NS[4]   = {8192, 4096, 2048, 1024};
    const int   SOFF[4] = {0, 16384, 24576, 28672};
    const float AB[4]   = {0.01f, 0.02f, 0.04f, 0.08f};
    int bx = blockIdx.x;
    int s, rel;
    if      (bx < 3072) { s = 0; rel = bx; }
    else if (bx < 4608) { s = 1; rel = bx - 3072; }
    else if (bx < 5376) { s = 2; rel = bx - 4608; }
    else                { s = 3; rel = bx - 5376; }
    const int N = NS[s];
    const int perType = N >> 3;
    int type = rel / perType;
    int blk = rel - type * perType;

    int lane = threadIdx.x & 31, w = threadIdx.x >> 5;
    int qg = blk * 16 + w * 2;
    int b = (qg >= N);
    int n0 = qg - (b ? N : 0);
    int base = SOFF[s] + (b ? N : 0);

    __shared__ float acc;
    if (threadIdx.x == 0) acc = 0.0f;
    __syncthreads();
    float contrib = 0.0f;

    if (type == 0) {
        const float4* P = g_s2 + base;
        float4 q0 = P[n0], q1 = P[n0 + 1];
        float d0, d1; int p0, p1v;
        windowKNN<10>(P, N, lane, q0, q1, n0, d0, p0, d1, p1v);
#pragma unroll
        for (int qq = 0; qq < 2; ++qq) {
            int pp = qq ? p1v : p0;
            float sx = 0.f, sy = 0.f, sz = 0.f;
            if (lane < 10) { float4 nb = __ldg(&P[pp]); sx = nb.x; sy = nb.y; sz = nb.z; }
            sx = wsum32(sx); sy = wsum32(sy); sz = wsum32(sz);
            if (lane == 0) {
                float4 q = qq ? q1 : q0;
                const float inv9 = 1.0f / 9.0f;
                g_cv2[base + n0 + qq] = make_float4((sx - 10.0f * q.x) * inv9,
                                                    (sy - 10.0f * q.y) * inv9,
                                                    (sz - 10.0f * q.z) * inv9, 0.0f);
            }
        }
    } else if (type == 1) {
        const float4* P = g_s1p + base;
        const float4* W = g_s1w + base;
        float4 q0 = P[n0], q1 = P[n0 + 1];
        float d0, d1; int p0, p1v;
        windowKNN<10>(P, N, lane, q0, q1, n0, d0, p0, d1, p1v);
#pragma unroll
        for (int qq = 0; qq < 2; ++qq) {
            int pp = qq ? p1v : p0;
            const int n = n0 + qq;
            float4 qP = qq ? q1 : q0;
            float4 qW = __ldg(&W[n]);
            float flqx = qW.x - qP.x, flqy = qW.y - qP.y, flqz = qW.z - qP.z;
            float sx = 0.f, sy = 0.f, sz = 0.f, sm = 0.f;
            if (lane < 10) {
                float4 nw = __ldg(&W[pp]);
                sx = nw.x; sy = nw.y; sz = nw.z;
                if (lane < 9) {
                    float4 np = __ldg(&P[pp]);
                    float fx = (nw.x - np.x) - flqx;
                    float fy = (nw.y - np.y) - flqy;
                    float fz = (nw.z - np.z) - flqz;
                    sm = sqrtf(fmaf(fx, fx, fmaf(fy, fy, fz * fz)));
                }
            }
            sx = wsum32(sx); sy = wsum32(sy); sz = wsum32(sz); sm = wsum32(sm);
            if (lane == 0) {
                const float inv9 = 1.0f / 9.0f;
                g_cvw[base + n] = make_float4((sx - 10.0f * qW.x) * inv9,
                                              (sy - 10.0f * qW.y) * inv9,
                                              (sz - 10.0f * qW.z) * inv9, 0.0f);
                contrib += AB[s] * sm * 0.125f;
            }
        }
    } else {
        const float4* R = g_sw + base;
        const float4* Q = g_s2 + base;
        float4 q0 = Q[n0], q1 = Q[n0 + 1];
        int start = searchPos((const float*)R, N, q0.x, lane);
        float d0, d1; int p0, p1v;
        windowKNN<1>(R, N, lane, q0, q1, start, d0, p0, d1, p1v);
        float m0 = __shfl_sync(FULLM, d0, 0);
        float m1 = __shfl_sync(FULLM, d1, 0);
        if (lane == 0) contrib = AB[s] * (m0 + m1);
    }

    if (lane == 0 && contrib != 0.0f) atomicAdd(&acc, contrib);
    __syncthreads();
    if (threadIdx.x == 0 && acc != 0.0f) atomicAdd(out, acc);
}

// ---------------------------------------------------------------------------
// C: kNN(warp->p2, 5): chamfer dist1 + curvature.
// ---------------------------------------------------------------------------
__global__ void __launch_bounds__(TB)
kC(float* __restrict__ out) {
    const int   NS[4]   = {8192, 4096, 2048, 1024};
    const int   SOFF[4] = {0, 16384, 24576, 28672};
    const float AB[4]   = {0.01f, 0.02f, 0.04f, 0.08f};
    int bx = blockIdx.x;
    int s, blk;
    if      (bx < 1024) { s = 0; blk = bx; }
    else if (bx < 1536) { s = 1; blk = bx - 1024; }
    else if (bx < 1792) { s = 2; blk = bx - 1536; }
    else                { s = 3; blk = bx - 1792; }
    const int N = NS[s];
    const float w_ch = AB[s];
    const float w_cv = 0.3f * AB[s];

    int lane = threadIdx.x & 31, w = threadIdx.x >> 5;
    int qg = blk * 16 + w * 2;
    int b = (qg >= N);
    int n0 = qg - (b ? N : 0);
    int base = SOFF[s] + (b ? N : 0);

    const float4* R = g_s2 + base;
    const float4* Wq = g_s1w + base;
    float4 q0 = Wq[n0], q1 = Wq[n0 + 1];
    int start = searchPos((const float*)R, N, q0.x, lane);

    float d0, d1; int p0, p1v;
    windowKNN<5>(R, N, lane, q0, q1, start, d0, p0, d1, p1v);

    float lossw = 0.0f;
#pragma unroll
    for (int qq = 0; qq < 2; ++qq) {
        float dd = qq ? d1 : d0;
        int pp = qq ? p1v : p0;
        float dist1 = __shfl_sync(FULLM, dd, 0);

        float wgt = 0.0f;
        float4 cc = make_float4(0.f, 0.f, 0.f, 0.f);
        if (lane < 5) {
            wgt = 1.0f / (dd + 1e-8f);
            cc = __ldg(&g_cv2[base + pp]);
        }
        float wsum = wsum32(wgt);
        float px = 0.f, py = 0.f, pz = 0.f;
        if (lane < 5) {
            float ww = wgt / wsum;
            px = ww * cc.x; py = ww * cc.y; pz = ww * cc.z;
        }
        float ix = wsum32(px), iy = wsum32(py), iz = wsum32(pz);
        if (lane == 0) {
            float4 cw = g_cvw[base + n0 + qq];
            float ex = ix - cw.x, ey = iy - cw.y, ez = iz - cw.z;
            float curv = fmaf(ex, ex, fmaf(ey, ey, ez * ez));
            lossw += w_ch * dist1 + w_cv * curv;
        }
    }

    __shared__ float acc;
    if (threadIdx.x == 0) acc = 0.0f;
    __syncthreads();
    if (lane == 0) atomicAdd(&acc, lossw);
    __syncthreads();
    if (threadIdx.x == 0) atomicAdd(out, acc);
}

// ---------------------------------------------------------------------------

extern "C" void kernel_launch(void* const* d_in, const int* in_sizes, int n_in,
                              void* d_out, int out_size) {
    float* out = (float*)d_out;
    InPtrs in;
    for (int i = 0; i < 12; ++i) in.p[i] = (const float*)d_in[i];

    kSortAll<<<24, NB>>>(in, out);
    kABD<<<5760, TB>>>(out);
    kC<<<1920, TB>>>(out);
}

// round 7
// speedup vs baseline: 8.0575x; 1.0116x over previous
#include <cuda_runtime.h>
#include <math.h>
#include <float.h>

// ---------------------------------------------------------------------------
// PointPWC multi-scale loss — bin-sorted-window exact kNN.
// Round 7: bitonic warm-up, direct bin-start lookup, shfl-scan sort.
// ---------------------------------------------------------------------------

#define TB 256
#define FULLM 0xffffffffu
#define NB 1024
#define XLO (-6.0f)
#define XSCALE (1024.0f / 12.0f)
#define BW 0.01171875f

__device__ float4 g_s1p[30720];   // p1 sorted by p1.x
__device__ float4 g_s1w[30720];   // warp, in p1.x-sorted order
__device__ float4 g_s2 [30720];   // p2 sorted by p2.x
__device__ float4 g_sw [30720];   // warp sorted by warp.x
__device__ float4 g_cv2[30720];
__device__ float4 g_cvw[30720];
__device__ int    g_binstart[24 * NB];   // exclusive prefix per group

struct InPtrs { const float* p[12]; };

__device__ __forceinline__ float wsum32(float v) {
#pragma unroll
    for (int o = 16; o; o >>= 1) v += __shfl_xor_sync(FULLM, v, o);
    return v;
}

// Warp bitonic sort of (d, p) ascending by (d, p). 15 stages.
__device__ __forceinline__ void bitonic32(int lane, float& d, int& p) {
#pragma unroll
    for (int k = 2; k <= 32; k <<= 1) {
#pragma unroll
        for (int j = k >> 1; j > 0; j >>= 1) {
            float od = __shfl_xor_sync(FULLM, d, j);
            int   op = __shfl_xor_sync(FULLM, p, j);
            bool lower = ((lane & j) == 0);
            bool up    = ((lane & k) == 0);
            bool less  = (od < d) || (od == d && op < p);
            if (less == (lower == up)) { d = od; p = op; }
        }
    }
}

// ---------------------------------------------------------------------------
// One-kernel counting sort: 24 blocks, one (scale,batch,array) group each.
// ---------------------------------------------------------------------------
__global__ void __launch_bounds__(NB)
kSortAll(InPtrs in, float* __restrict__ out) {
    __shared__ int hist[NB];
    __shared__ int wsums[NB / 32];
    const int NS[4]   = {8192, 4096, 2048, 1024};
    const int SOFF[4] = {0, 16384, 24576, 28672};
    int g = blockIdx.x;
    if (g == 0 && threadIdx.x == 0) out[0] = 0.0f;
    int s = g / 6, rem = g % 6, b = rem / 3, arr = rem % 3;
    const int N = NS[s];
    const float* P1 = in.p[s]     + (size_t)b * 3 * N;
    const float* P2 = in.p[4 + s] + (size_t)b * 3 * N;
    const float* F  = in.p[8 + s] + (size_t)b * 3 * N;
    const int t = threadIdx.x;
    const int lane = t & 31, w = t >> 5;

    hist[t] = 0;
    __syncthreads();

    for (int i = t; i < N; i += NB) {
        float x;
        if      (arr == 0) x = P1[i];
        else if (arr == 1) x = P2[i];
        else               x = P1[i] + F[i];
        int bin = (int)((x - XLO) * XSCALE);
        bin = min(NB - 1, max(0, bin));
        atomicAdd(&hist[bin], 1);
    }
    __syncthreads();

    // two-level shfl scan
    int cnt = hist[t];
    int v = cnt;
#pragma unroll
    for (int o = 1; o < 32; o <<= 1) {
        int u = __shfl_up_sync(FULLM, v, o);
        if (lane >= o) v += u;
    }
    if (lane == 31) wsums[w] = v;
    __syncthreads();
    if (t < 32) {
        int wv = wsums[t];
#pragma unroll
        for (int o = 1; o < 32; o <<= 1) {
            int u = __shfl_up_sync(FULLM, wv, o);
            if (t >= o) wv += u;
        }
        wsums[t] = wv;
    }
    __syncthreads();
    int excl = v - cnt + (w > 0 ? wsums[w - 1] : 0);
    g_binstart[g * NB + t] = excl;
    hist[t] = excl;
    __syncthreads();

    int gbase = SOFF[s] + b * N;
    for (int i = t; i < N; i += NB) {
        float x, y, z;
        if (arr == 0)      { x = P1[i]; y = P1[i + N]; z = P1[i + 2 * N]; }
        else if (arr == 1) { x = P2[i]; y = P2[i + N]; z = P2[i + 2 * N]; }
        else { x = P1[i] + F[i]; y = P1[i + N] + F[i + N]; z = P1[i + 2 * N] + F[i + 2 * N]; }
        int bin = (int)((x - XLO) * XSCALE);
        bin = min(NB - 1, max(0, bin));
        int pos = atomicAdd(&hist[bin], 1);
        int dst = gbase + pos;
        if (arr == 0) {
            g_s1p[dst] = make_float4(x, y, z, fmaf(x, x, fmaf(y, y, z * z)));
            float wx = x + F[i], wy = y + F[i + N], wz = z + F[i + 2 * N];
            g_s1w[dst] = make_float4(wx, wy, wz, fmaf(wx, wx, fmaf(wy, wy, wz * wz)));
        } else if (arr == 1) {
            g_s2[dst] = make_float4(x, y, z, fmaf(x, x, fmaf(y, y, z * z)));
        } else {
            g_sw[dst] = make_float4(x, y, z, fmaf(x, x, fmaf(y, y, z * z)));
        }
    }
}

// One insert-event pass over per-lane candidate register u (positions pp).
template <int K>
__device__ __forceinline__ void eventLoop(int lane, float& u, int pp,
                                          float& ld, int& lp, float& g) {
    for (;;) {
        unsigned bal = __ballot_sync(FULLM, u < g);
        if (!bal) break;
        int src = __ffs(bal) - 1;
        float bt = __shfl_sync(FULLM, u, src);
        int   bp = __shfl_sync(FULLM, pp, src);
        if (lane == src) u = FLT_MAX;
        bool ins = (lane < K) && (bt < ld);
        unsigned im = __ballot_sync(FULLM, ins);
        float pd = __shfl_up_sync(FULLM, ld, 1);
        int   pi = __shfl_up_sync(FULLM, lp, 1);
        bool pins = (lane > 0) && ((im >> (lane - 1)) & 1u);
        if (ins) { ld = pins ? pd : bt; lp = pins ? pi : bp; }
        g = __shfl_sync(FULLM, ld, K - 1);
    }
}

// ---------------------------------------------------------------------------
// Window kNN for 2 queries, proxy edges, 64-point expansion chunks,
// bitonic warm-up. Lane r ends with r-th nearest (true sqdist, ascending).
// ---------------------------------------------------------------------------
template <int K>
__device__ __forceinline__ void windowKNN(
    const float4* __restrict__ R, int N, int lane,
    float4 q0, float4 q1, int start,
    float& od0, int& op0, float& od1, int& op1)
{
    const float a0 = -2.f * q0.x, b0 = -2.f * q0.y, c0 = -2.f * q0.z;
    const float a1 = -2.f * q1.x, b1 = -2.f * q1.y, c1 = -2.f * q1.z;

    int c = start - 15;
    if (c < 0) c = 0;
    if (c > N - 32) c = N - 32;

    // ---- warm-up chunk (32, fully in range) ----
    int pos = c + lane;
    float4 rp = __ldg(&R[pos]);
    float t0 = fmaf(a0, rp.x, fmaf(b0, rp.y, fmaf(c0, rp.z, rp.w + q0.w)));
    float t1 = fmaf(a1, rp.x, fmaf(b1, rp.y, fmaf(c1, rp.z, rp.w + q1.w)));
    float xL = __shfl_sync(FULLM, rp.x, 0);
    float xR = __shfl_sync(FULLM, rp.x, 31);

    float ld0, ld1; int lp0, lp1; float g0, g1;
    if (K == 1) {
        float m0 = t0, m1 = t1;
        int j0 = pos, j1 = pos;
#pragma unroll
        for (int o = 16; o; o >>= 1) {
            float om = __shfl_xor_sync(FULLM, m0, o);
            int   oj = __shfl_xor_sync(FULLM, j0, o);
            if (om < m0 || (om == m0 && oj < j0)) { m0 = om; j0 = oj; }
            float pm = __shfl_xor_sync(FULLM, m1, o);
            int   pj = __shfl_xor_sync(FULLM, j1, o);
            if (pm < m1 || (pm == m1 && pj < j1)) { m1 = pm; j1 = pj; }
        }
        ld0 = (lane == 0) ? m0 : FLT_MAX; lp0 = j0; g0 = m0;
        ld1 = (lane == 0) ? m1 : FLT_MAX; lp1 = j1; g1 = m1;
    } else {
        float sd0 = t0; int sp0 = pos;
        bitonic32(lane, sd0, sp0);
        ld0 = (lane < K) ? sd0 : FLT_MAX; lp0 = sp0;
        g0 = __shfl_sync(FULLM, sd0, K - 1);
        float sd1 = t1; int sp1 = pos;
        bitonic32(lane, sd1, sp1);
        ld1 = (lane < K) ? sd1 : FLT_MAX; lp1 = sp1;
        g1 = __shfl_sync(FULLM, sd1, K - 1);
    }

    int l = c - 1, r = c + 32;
    bool ldone = (l < 0), rdone = (r >= N);

    for (;;) {
        if (!ldone) {
            float dl0 = q0.x - xL - BW, dl1 = q1.x - xL - BW;
            ldone = (l < 0) || ((dl0 >= 0.f) & (dl0 * dl0 >= g0) &
                                (dl1 >= 0.f) & (dl1 * dl1 >= g1));
        }
        if (!rdone) {
            float dr0 = xR - BW - q0.x, dr1 = xR - BW - q1.x;
            rdone = (r >= N) || ((dr0 >= 0.f) & (dr0 * dr0 >= g0) &
                                 (dr1 >= 0.f) & (dr1 * dr1 >= g1));
        }
        if (ldone && rdone) break;

        bool goLeft = !ldone && (rdone || (q0.x - xL) <= (xR - q0.x));
        int pbase;
        if (goLeft) { pbase = l - 63; l -= 64; }
        else        { pbase = r;      r += 64; }

        int pa = pbase + lane, pb = pbase + 32 + lane;
        bool va = (pa >= 0) & (pa < N);
        bool vb = (pb >= 0) & (pb < N);
        float4 ra = __ldg(&R[va ? pa : 0]);
        float4 rb = __ldg(&R[vb ? pb : 0]);
        if (goLeft) xL = __shfl_sync(FULLM, ra.x, 0);
        else        xR = __shfl_sync(FULLM, rb.x, 31);

        float u0a = fmaf(a0, ra.x, fmaf(b0, ra.y, fmaf(c0, ra.z, ra.w + q0.w)));
        float u1a = fmaf(a1, ra.x, fmaf(b1, ra.y, fmaf(c1, ra.z, ra.w + q1.w)));
        float u0b = fmaf(a0, rb.x, fmaf(b0, rb.y, fmaf(c0, rb.z, rb.w + q0.w)));
        float u1b = fmaf(a1, rb.x, fmaf(b1, rb.y, fmaf(c1, rb.z, rb.w + q1.w)));
        if (!va) { u0a = FLT_MAX; u1a = FLT_MAX; }
        if (!vb) { u0b = FLT_MAX; u1b = FLT_MAX; }

        eventLoop<K>(lane, u0a, pa, ld0, lp0, g0);
        eventLoop<K>(lane, u0b, pb, ld0, lp0, g0);
        eventLoop<K>(lane, u1a, pa, ld1, lp1, g1);
        eventLoop<K>(lane, u1b, pb, ld1, lp1, g1);
    }
    od0 = ld0; op0 = lp0; od1 = ld1; op1 = lp1;
}

// ---------------------------------------------------------------------------
// Fused A/B/D
// ---------------------------------------------------------------------------
__global__ void __launch_bounds__(TB)
kABD(float* __restrict__ out) {
    const int   NS[4]   = {8192, 4096, 2048, 1024};
    const int   SOFF[4] = {0, 16384, 24576, 28672};
    const float AB[4]   = {0.01f, 0.02f, 0.04f, 0.08f};
    int bx = blockIdx.x;
    int s, rel;
    if      (bx < 3072) { s = 0; rel = bx; }
    else if (bx < 4608) { s = 1; rel = bx - 3072; }
    else if (bx < 5376) { s = 2; rel = bx - 4608; }
    else                { s = 3; rel = bx - 5376; }
    const int N = NS[s];
    const int perType = N >> 3;
    int type = rel / perType;
    int blk = rel - type * perType;

    int lane = threadIdx.x & 31, w = threadIdx.x >> 5;
    int qg = blk * 16 + w * 2;
    int b = (qg >= N);
    int n0 = qg - (b ? N : 0);
    int base = SOFF[s] + (b ? N : 0);

    __shared__ float acc;
    if (threadIdx.x == 0) acc = 0.0f;
    __syncthreads();
    float contrib = 0.0f;

    if (type == 0) {
        const float4* P = g_s2 + base;
        float4 q0 = P[n0], q1 = P[n0 + 1];
        float d0, d1; int p0, p1v;
        windowKNN<10>(P, N, lane, q0, q1, n0, d0, p0, d1, p1v);
#pragma unroll
        for (int qq = 0; qq < 2; ++qq) {
            int pp = qq ? p1v : p0;
            float sx = 0.f, sy = 0.f, sz = 0.f;
            if (lane < 10) { float4 nb = __ldg(&P[pp]); sx = nb.x; sy = nb.y; sz = nb.z; }
            sx = wsum32(sx); sy = wsum32(sy); sz = wsum32(sz);
            if (lane == 0) {
                float4 q = qq ? q1 : q0;
                const float inv9 = 1.0f / 9.0f;
                g_cv2[base + n0 + qq] = make_float4((sx - 10.0f * q.x) * inv9,
                                                    (sy - 10.0f * q.y) * inv9,
                                                    (sz - 10.0f * q.z) * inv9, 0.0f);
            }
        }
    } else if (type == 1) {
        const float4* P = g_s1p + base;
        const float4* W = g_s1w + base;
        float4 q0 = P[n0], q1 = P[n0 + 1];
        float d0, d1; int p0, p1v;
        windowKNN<10>(P, N, lane, q0, q1, n0, d0, p0, d1, p1v);
#pragma unroll
        for (int qq = 0; qq < 2; ++qq) {
            int pp = qq ? p1v : p0;
            const int n = n0 + qq;
            float4 qP = qq ? q1 : q0;
            float4 qW = __ldg(&W[n]);
            float flqx = qW.x - qP.x, flqy = qW.y - qP.y, flqz = qW.z - qP.z;
            float sx = 0.f, sy = 0.f, sz = 0.f, sm = 0.f;
            if (lane < 10) {
                float4 nw = __ldg(&W[pp]);
                sx = nw.x; sy = nw.y; sz = nw.z;
                if (lane < 9) {
                    float4 np = __ldg(&P[pp]);
                    float fx = (nw.x - np.x) - flqx;
                    float fy = (nw.y - np.y) - flqy;
                    float fz = (nw.z - np.z) - flqz;
                    sm = sqrtf(fmaf(fx, fx, fmaf(fy, fy, fz * fz)));
                }
            }
            sx = wsum32(sx); sy = wsum32(sy); sz = wsum32(sz); sm = wsum32(sm);
            if (lane == 0) {
                const float inv9 = 1.0f / 9.0f;
                g_cvw[base + n] = make_float4((sx - 10.0f * qW.x) * inv9,
                                              (sy - 10.0f * qW.y) * inv9,
                                              (sz - 10.0f * qW.z) * inv9, 0.0f);
                contrib += AB[s] * sm * 0.125f;
            }
        }
    } else {
        const float4* R = g_sw + base;
        const float4* Q = g_s2 + base;
        float4 q0 = Q[n0], q1 = Q[n0 + 1];
        int bin = (int)((q0.x - XLO) * XSCALE);
        bin = min(NB - 1, max(0, bin));
        int gidx = ((s * 2 + b) * 3 + 2) * NB + bin;
        int start = __ldg(&g_binstart[gidx]);
        float d0, d1; int p0, p1v;
        windowKNN<1>(R, N, lane, q0, q1, start, d0, p0, d1, p1v);
        float m0 = __shfl_sync(FULLM, d0, 0);
        float m1 = __shfl_sync(FULLM, d1, 0);
        if (lane == 0) contrib = AB[s] * (m0 + m1);
    }

    if (lane == 0 && contrib != 0.0f) atomicAdd(&acc, contrib);
    __syncthreads();
    if (threadIdx.x == 0 && acc != 0.0f) atomicAdd(out, acc);
}

// ---------------------------------------------------------------------------
// C: kNN(warp->p2, 5): chamfer dist1 + curvature.
// ---------------------------------------------------------------------------
__global__ void __launch_bounds__(TB)
kC(float* __restrict__ out) {
    const int   NS[4]   = {8192, 4096, 2048, 1024};
    const int   SOFF[4] = {0, 16384, 24576, 28672};
    const float AB[4]   = {0.01f, 0.02f, 0.04f, 0.08f};
    int bx = blockIdx.x;
    int s, blk;
    if      (bx < 1024) { s = 0; blk = bx; }
    else if (bx < 1536) { s = 1; blk = bx - 1024; }
    else if (bx < 1792) { s = 2; blk = bx - 1536; }
    else                { s = 3; blk = bx - 1792; }
    const int N = NS[s];
    const float w_ch = AB[s];
    const float w_cv = 0.3f * AB[s];

    int lane = threadIdx.x & 31, w = threadIdx.x >> 5;
    int qg = blk * 16 + w * 2;
    int b = (qg >= N);
    int n0 = qg - (b ? N : 0);
    int base = SOFF[s] + (b ? N : 0);

    const float4* R = g_s2 + base;
    const float4* Wq = g_s1w + base;
    float4 q0 = Wq[n0], q1 = Wq[n0 + 1];
    int bin = (int)((q0.x - XLO) * XSCALE);
    bin = min(NB - 1, max(0, bin));
    int gidx = ((s * 2 + b) * 3 + 1) * NB + bin;
    int start = __ldg(&g_binstart[gidx]);

    float d0, d1; int p0, p1v;
    windowKNN<5>(R, N, lane, q0, q1, start, d0, p0, d1, p1v);

    float lossw = 0.0f;
#pragma unroll
    for (int qq = 0; qq < 2; ++qq) {
        float dd = qq ? d1 : d0;
        int pp = qq ? p1v : p0;
        float dist1 = __shfl_sync(FULLM, dd, 0);

        float wgt = 0.0f;
        float4 cc = make_float4(0.f, 0.f, 0.f, 0.f);
        if (lane < 5) {
            wgt = 1.0f / (dd + 1e-8f);
            cc = __ldg(&g_cv2[base + pp]);
        }
        float wsum = wsum32(wgt);
        float px = 0.f, py = 0.f, pz = 0.f;
        if (lane < 5) {
            float ww = wgt / wsum;
            px = ww * cc.x; py = ww * cc.y; pz = ww * cc.z;
        }
        float ix = wsum32(px), iy = wsum32(py), iz = wsum32(pz);
        if (lane == 0) {
            float4 cw = g_cvw[base + n0 + qq];
            float ex = ix - cw.x, ey = iy - cw.y, ez = iz - cw.z;
            float curv = fmaf(ex, ex, fmaf(ey, ey, ez * ez));
            lossw += w_ch * dist1 + w_cv * curv;
        }
    }

    __shared__ float acc;
    if (threadIdx.x == 0) acc = 0.0f;
    __syncthreads();
    if (lane == 0) atomicAdd(&acc, lossw);
    __syncthreads();
    if (threadIdx.x == 0) atomicAdd(out, acc);
}

// ---------------------------------------------------------------------------

extern "C" void kernel_launch(void* const* d_in, const int* in_sizes, int n_in,
                              void* d_out, int out_size) {
    float* out = (float*)d_out;
    InPtrs in;
    for (int i = 0; i < 12; ++i) in.p[i] = (const float*)d_in[i];

    kSortAll<<<24, NB>>>(in, out);
    kABD<<<5760, TB>>>(out);
    kC<<<1920, TB>>>(out);
}

// round 8
// speedup vs baseline: 9.1246x; 1.1324x over previous
#include <cuda_runtime.h>
#include <math.h>
#include <float.h>

// ---------------------------------------------------------------------------
// PointPWC multi-scale loss — 2D (x-slab, y-bin) sorted exact kNN.
//
// Points sorted by key = slab(x)*YB + ybin(y). Exact pruning:
//  - slab level: skip slab when dx_edge^2 >= gate (exact slab edges)
//  - y level: points beyond left edge have y < binHi(edge lane0);
//             beyond right edge have y >= binLo(edge lane31).
// Warm-up = flat 32-chunk around query (finite gate); slab scans exclude the
// warm-up flat interval to avoid double counting.
// ---------------------------------------------------------------------------

#define TB 256
#define FULLM 0xffffffffu
#define XS 64
#define YB 160
#define NBIN2 (XS * YB)          // 10240
#define XLO (-6.0f)
#define YLO (-6.0f)
#define SW  (12.0f / XS)         // 0.1875
#define YW  (12.0f / YB)         // 0.075
#define XSC (XS / 12.0f)
#define YSC (YB / 12.0f)

__device__ float4 g_s1p[30720];
__device__ float4 g_s1w[30720];
__device__ float4 g_s2 [30720];
__device__ float4 g_sw [30720];
__device__ float4 g_cv2[30720];
__device__ float4 g_cvw[30720];
__device__ int    g_binstart[24 * NBIN2];

struct InPtrs { const float* p[12]; };

__device__ __forceinline__ float wsum32(float v) {
#pragma unroll
    for (int o = 16; o; o >>= 1) v += __shfl_xor_sync(FULLM, v, o);
    return v;
}

__device__ __forceinline__ int slabOf(float x) {
    int s = (int)((x - XLO) * XSC);
    return min(XS - 1, max(0, s));
}
__device__ __forceinline__ int ybinOf(float y) {
    int b = (int)((y - YLO) * YSC);
    return min(YB - 1, max(0, b));
}
__device__ __forceinline__ float dxsqSlab(float qx, int sl) {
    float lo = XLO + sl * SW, hi = lo + SW;
    float d = fmaxf(0.0f, fmaxf(lo - qx, qx - hi));
    return d * d;
}

// Warp bitonic sort of (d, p) ascending. 15 stages.
__device__ __forceinline__ void bitonic32(int lane, float& d, int& p) {
#pragma unroll
    for (int k = 2; k <= 32; k <<= 1) {
#pragma unroll
        for (int j = k >> 1; j > 0; j >>= 1) {
            float od = __shfl_xor_sync(FULLM, d, j);
            int   op = __shfl_xor_sync(FULLM, p, j);
            bool lower = ((lane & j) == 0);
            bool up    = ((lane & k) == 0);
            bool less  = (od < d) || (od == d && op < p);
            if (less == (lower == up)) { d = od; p = op; }
        }
    }
}

// One insert-event pass over per-lane candidate u (flat positions pp).
template <int K>
__device__ __forceinline__ void eventLoop(int lane, float& u, int pp,
                                          float& ld, int& lp, float& g) {
    for (;;) {
        unsigned bal = __ballot_sync(FULLM, u < g);
        if (!bal) break;
        int src = __ffs(bal) - 1;
        float bt = __shfl_sync(FULLM, u, src);
        int   bp = __shfl_sync(FULLM, pp, src);
        if (lane == src) u = FLT_MAX;
        bool ins = (lane < K) && (bt < ld);
        unsigned im = __ballot_sync(FULLM, ins);
        float pd = __shfl_up_sync(FULLM, ld, 1);
        int   pi = __shfl_up_sync(FULLM, lp, 1);
        bool pins = (lane > 0) && ((im >> (lane - 1)) & 1u);
        if (ins) { ld = pins ? pd : bt; lp = pins ? pi : bp; }
        g = __shfl_sync(FULLM, ld, K - 1);
    }
}

// ---------------------------------------------------------------------------
// y-window scan of one slab for 2 queries, excluding flat [wlo, whi).
// ---------------------------------------------------------------------------
template <int K>
__device__ void scanSlab(const float4* __restrict__ R, const int* __restrict__ bs,
                         int N, int lane, int sl,
                         float dx0, float dx1,     // squared slab distances
                         float4 q0, float4 q1, int wlo, int whi,
                         float& ld0, int& lp0, float& g0,
                         float& ld1, int& lp1, float& g1) {
    int sbeg = __ldg(&bs[sl * YB]);
    int send = (sl == XS - 1) ? N : __ldg(&bs[(sl + 1) * YB]);
    if (sbeg >= send) return;

    const float a0 = -2.f * q0.x, b0 = -2.f * q0.y, c0 = -2.f * q0.z;
    const float a1 = -2.f * q1.x, b1 = -2.f * q1.y, c1 = -2.f * q1.z;

    int yb = ybinOf(q0.y);
    int st = __ldg(&bs[sl * YB + yb]);
    st = min(max(st, sbeg), send);
    int l = st - 1, r = st;
    float upperL = YLO + yb * YW;   // points idx < st have y < this
    float lowerR = YLO + yb * YW;   // points idx >= st have y >= this

    for (;;) {
        bool ldone, rdone;
        {
            float e0 = q0.y - upperL, e1 = q1.y - upperL;
            ldone = (l < sbeg) ||
                    ((e0 >= 0.f) & (fmaf(e0, e0, dx0) >= g0) &
                     (e1 >= 0.f) & (fmaf(e1, e1, dx1) >= g1));
            float f0 = lowerR - q0.y, f1 = lowerR - q1.y;
            rdone = (r >= send) ||
                    ((f0 >= 0.f) & (fmaf(f0, f0, dx0) >= g0) &
                     (f1 >= 0.f) & (fmaf(f1, f1, dx1) >= g1));
        }
        if (ldone && rdone) break;

        bool goLeft = !ldone && (rdone || (q0.y - upperL) <= (lowerR - q0.y));
        int pbase;
        if (goLeft) { pbase = l - 31; l -= 32; }
        else        { pbase = r;      r += 32; }

        int pos = pbase + lane;
        bool inRange = (pos >= sbeg) & (pos < send);
        bool valid = inRange & ((pos < wlo) | (pos >= whi));
        float4 ra = __ldg(&R[inRange ? pos : sbeg]);
        if (goLeft) {
            float y0 = __shfl_sync(FULLM, ra.y, 0);
            upperL = YLO + (ybinOf(y0) + 1) * YW;
        } else {
            float y31 = __shfl_sync(FULLM, ra.y, 31);
            lowerR = YLO + ybinOf(y31) * YW;
        }
        float u0 = fmaf(a0, ra.x, fmaf(b0, ra.y, fmaf(c0, ra.z, ra.w + q0.w)));
        float u1 = fmaf(a1, ra.x, fmaf(b1, ra.y, fmaf(c1, ra.z, ra.w + q1.w)));
        if (!valid) { u0 = FLT_MAX; u1 = FLT_MAX; }

        eventLoop<K>(lane, u0, pos, ld0, lp0, g0);
        eventLoop<K>(lane, u1, pos, ld1, lp1, g1);
    }
}

// ---------------------------------------------------------------------------
// 2D window kNN for 2 (adjacent) queries. Lane r -> r-th nearest, ascending.
// ---------------------------------------------------------------------------
template <int K>
__device__ void windowKNN2D(const float4* __restrict__ R, int N,
                            const int* __restrict__ bs, int lane,
                            float4 q0, float4 q1, int flatStart,
                            float& od0, int& op0, float& od1, int& op1) {
    const float a0 = -2.f * q0.x, b0 = -2.f * q0.y, c0 = -2.f * q0.z;
    const float a1 = -2.f * q1.x, b1 = -2.f * q1.y, c1 = -2.f * q1.z;

    int c = flatStart - 15;
    if (c < 0) c = 0;
    if (c > N - 32) c = N - 32;
    int pos = c + lane;
    float4 rp = __ldg(&R[pos]);
    float t0 = fmaf(a0, rp.x, fmaf(b0, rp.y, fmaf(c0, rp.z, rp.w + q0.w)));
    float t1 = fmaf(a1, rp.x, fmaf(b1, rp.y, fmaf(c1, rp.z, rp.w + q1.w)));

    float ld0, ld1; int lp0, lp1; float g0, g1;
    if (K == 1) {
        float m0 = t0, m1 = t1;
        int j0 = pos, j1 = pos;
#pragma unroll
        for (int o = 16; o; o >>= 1) {
            float om = __shfl_xor_sync(FULLM, m0, o);
            int   oj = __shfl_xor_sync(FULLM, j0, o);
            if (om < m0 || (om == m0 && oj < j0)) { m0 = om; j0 = oj; }
            float pm = __shfl_xor_sync(FULLM, m1, o);
            int   pj = __shfl_xor_sync(FULLM, j1, o);
            if (pm < m1 || (pm == m1 && pj < j1)) { m1 = pm; j1 = pj; }
        }
        ld0 = (lane == 0) ? m0 : FLT_MAX; lp0 = j0; g0 = m0;
        ld1 = (lane == 0) ? m1 : FLT_MAX; lp1 = j1; g1 = m1;
    } else {
        float sd0 = t0; int sp0 = pos;
        bitonic32(lane, sd0, sp0);
        ld0 = (lane < K) ? sd0 : FLT_MAX; lp0 = sp0;
        g0 = __shfl_sync(FULLM, sd0, K - 1);
        float sd1 = t1; int sp1 = pos;
        bitonic32(lane, sd1, sp1);
        ld1 = (lane < K) ? sd1 : FLT_MAX; lp1 = sp1;
        g1 = __shfl_sync(FULLM, sd1, K - 1);
    }

    const int wlo = c, whi = c + 32;
    const int sl0 = slabOf(q0.x);

    // own slab (dx may be nonzero for q1)
    scanSlab<K>(R, bs, N, lane, sl0, dxsqSlab(q0.x, sl0), dxsqSlab(q1.x, sl0),
                q0, q1, wlo, whi, ld0, lp0, g0, ld1, lp1, g1);

    for (int ds = 1; ds < XS; ++ds) {
        bool any = false;
        int sl = sl0 - ds;
        if (sl >= 0) {
            float dx0 = dxsqSlab(q0.x, sl), dx1 = dxsqSlab(q1.x, sl);
            if (dx0 < g0 || dx1 < g1) {
                scanSlab<K>(R, bs, N, lane, sl, dx0, dx1, q0, q1, wlo, whi,
                            ld0, lp0, g0, ld1, lp1, g1);
                any = true;
            }
        }
        int sr = sl0 + ds;
        if (sr < XS) {
            float dx0 = dxsqSlab(q0.x, sr), dx1 = dxsqSlab(q1.x, sr);
            if (dx0 < g0 || dx1 < g1) {
                scanSlab<K>(R, bs, N, lane, sr, dx0, dx1, q0, q1, wlo, whi,
                            ld0, lp0, g0, ld1, lp1, g1);
                any = true;
            }
        }
        if (!any) break;
    }
    od0 = ld0; op0 = lp0; od1 = ld1; op1 = lp1;
}

// ---------------------------------------------------------------------------
// One-kernel 2D counting sort: 24 blocks, one (scale,batch,array) group each.
// ---------------------------------------------------------------------------
__global__ void __launch_bounds__(1024)
kSortAll(InPtrs in, float* __restrict__ out) {
    __shared__ int hist[NBIN2];
    __shared__ int wsums[32];
    const int NS[4]   = {8192, 4096, 2048, 1024};
    const int SOFF[4] = {0, 16384, 24576, 28672};
    int g = blockIdx.x;
    if (g == 0 && threadIdx.x == 0) out[0] = 0.0f;
    int s = g / 6, rem = g % 6, b = rem / 3, arr = rem % 3;
    const int N = NS[s];
    const float* P1 = in.p[s]     + (size_t)b * 3 * N;
    const float* P2 = in.p[4 + s] + (size_t)b * 3 * N;
    const float* F  = in.p[8 + s] + (size_t)b * 3 * N;
    const int t = threadIdx.x;
    const int lane = t & 31, w = t >> 5;
    const int PERT = NBIN2 / 1024;   // 10

#pragma unroll
    for (int j = 0; j < PERT; ++j) hist[t * PERT + j] = 0;
    __syncthreads();

    for (int i = t; i < N; i += 1024) {
        float x, y;
        if      (arr == 0) { x = P1[i]; y = P1[i + N]; }
        else if (arr == 1) { x = P2[i]; y = P2[i + N]; }
        else               { x = P1[i] + F[i]; y = P1[i + N] + F[i + N]; }
        atomicAdd(&hist[slabOf(x) * YB + ybinOf(y)], 1);
    }
    __syncthreads();

    // per-thread partials + two-level exclusive scan
    int loc[PERT]; int sum = 0;
#pragma unroll
    for (int j = 0; j < PERT; ++j) { loc[j] = hist[t * PERT + j]; sum += loc[j]; }
    int v = sum;
#pragma unroll
    for (int o = 1; o < 32; o <<= 1) {
        int u = __shfl_up_sync(FULLM, v, o);
        if (lane >= o) v += u;
    }
    if (lane == 31) wsums[w] = v;
    __syncthreads();
    if (t < 32) {
        int wv = wsums[t];
#pragma unroll
        for (int o = 1; o < 32; o <<= 1) {
            int u = __shfl_up_sync(FULLM, wv, o);
            if (t >= o) wv += u;
        }
        wsums[t] = wv;
    }
    __syncthreads();
    int run = v - sum + (w > 0 ? wsums[w - 1] : 0);
#pragma unroll
    for (int j = 0; j < PERT; ++j) {
        int ccc = loc[j];
        g_binstart[g * NBIN2 + t * PERT + j] = run;
        hist[t * PERT + j] = run;
        run += ccc;
    }
    __syncthreads();

    int gbase = SOFF[s] + b * N;
    for (int i = t; i < N; i += 1024) {
        float x, y, z;
        if (arr == 0)      { x = P1[i]; y = P1[i + N]; z = P1[i + 2 * N]; }
        else if (arr == 1) { x = P2[i]; y = P2[i + N]; z = P2[i + 2 * N]; }
        else { x = P1[i] + F[i]; y = P1[i + N] + F[i + N]; z = P1[i + 2 * N] + F[i + 2 * N]; }
        int bin = slabOf(x) * YB + ybinOf(y);
        int pos = atomicAdd(&hist[bin], 1);
        int dst = gbase + pos;
        if (arr == 0) {
            g_s1p[dst] = make_float4(x, y, z, fmaf(x, x, fmaf(y, y, z * z)));
            float wx = x + F[i], wy = y + F[i + N], wz = z + F[i + 2 * N];
            g_s1w[dst] = make_float4(wx, wy, wz, fmaf(wx, wx, fmaf(wy, wy, wz * wz)));
        } else if (arr == 1) {
            g_s2[dst] = make_float4(x, y, z, fmaf(x, x, fmaf(y, y, z * z)));
        } else {
            g_sw[dst] = make_float4(x, y, z, fmaf(x, x, fmaf(y, y, z * z)));
        }
    }
}

// ---------------------------------------------------------------------------
// kAB: type 0 = A (cv2 from p2 self-kNN 10), type 1 = B (cvw + smooth).
// ---------------------------------------------------------------------------
__global__ void __launch_bounds__(TB)
kAB(float* __restrict__ out) {
    const int   NS[4]   = {8192, 4096, 2048, 1024};
    const int   SOFF[4] = {0, 16384, 24576, 28672};
    const float AB[4]   = {0.01f, 0.02f, 0.04f, 0.08f};
    int bx = blockIdx.x;
    int s, rel;
    if      (bx < 2048) { s = 0; rel = bx; }
    else if (bx < 3072) { s = 1; rel = bx - 2048; }
    else if (bx < 3584) { s = 2; rel = bx - 3072; }
    else                { s = 3; rel = bx - 3584; }
    const int N = NS[s];
    const int perType = N >> 3;
    int type = rel / perType;
    int blk = rel - type * perType;

    int lane = threadIdx.x & 31, w = threadIdx.x >> 5;
    int qg = blk * 16 + w * 2;
    int b = (qg >= N);
    int n0 = qg - (b ? N : 0);
    int base = SOFF[s] + (b ? N : 0);
    int grp = (s * 2 + b) * 3;

    __shared__ float acc;
    if (threadIdx.x == 0) acc = 0.0f;
    __syncthreads();
    float contrib = 0.0f;

    if (type == 0) {
        const float4* P = g_s2 + base;
        const int* bs = g_binstart + (grp + 1) * NBIN2;
        float4 q0 = P[n0], q1 = P[n0 + 1];
        float d0, d1; int p0, p1v;
        windowKNN2D<10>(P, N, bs, lane, q0, q1, n0, d0, p0, d1, p1v);
#pragma unroll
        for (int qq = 0; qq < 2; ++qq) {
            int pp = qq ? p1v : p0;
            float sx = 0.f, sy = 0.f, sz = 0.f;
            if (lane < 10) { float4 nb = __ldg(&P[pp]); sx = nb.x; sy = nb.y; sz = nb.z; }
            sx = wsum32(sx); sy = wsum32(sy); sz = wsum32(sz);
            if (lane == 0) {
                float4 q = qq ? q1 : q0;
                const float inv9 = 1.0f / 9.0f;
                g_cv2[base + n0 + qq] = make_float4((sx - 10.0f * q.x) * inv9,
                                                    (sy - 10.0f * q.y) * inv9,
                                                    (sz - 10.0f * q.z) * inv9, 0.0f);
            }
        }
    } else {
        const float4* P = g_s1p + base;
        const float4* W = g_s1w + base;
        const int* bs = g_binstart + (grp + 0) * NBIN2;
        float4 q0 = P[n0], q1 = P[n0 + 1];
        float d0, d1; int p0, p1v;
        windowKNN2D<10>(P, N, bs, lane, q0, q1, n0, d0, p0, d1, p1v);
#pragma unroll
        for (int qq = 0; qq < 2; ++qq) {
            int pp = qq ? p1v : p0;
            const int n = n0 + qq;
            float4 qP = qq ? q1 : q0;
            float4 qW = __ldg(&W[n]);
            float flqx = qW.x - qP.x, flqy = qW.y - qP.y, flqz = qW.z - qP.z;
            float sx = 0.f, sy = 0.f, sz = 0.f, sm = 0.f;
            if (lane < 10) {
                float4 nw = __ldg(&W[pp]);
                sx = nw.x; sy = nw.y; sz = nw.z;
                if (lane < 9) {
                    float4 np = __ldg(&P[pp]);
                    float fx = (nw.x - np.x) - flqx;
                    float fy = (nw.y - np.y) - flqy;
                    float fz = (nw.z - np.z) - flqz;
                    sm = sqrtf(fmaf(fx, fx, fmaf(fy, fy, fz * fz)));
                }
            }
            sx = wsum32(sx); sy = wsum32(sy); sz = wsum32(sz); sm = wsum32(sm);
            if (lane == 0) {
                const float inv9 = 1.0f / 9.0f;
                g_cvw[base + n] = make_float4((sx - 10.0f * qW.x) * inv9,
                                              (sy - 10.0f * qW.y) * inv9,
                                              (sz - 10.0f * qW.z) * inv9, 0.0f);
                contrib += AB[s] * sm * 0.125f;
            }
        }
    }

    if (lane == 0 && contrib != 0.0f) atomicAdd(&acc, contrib);
    __syncthreads();
    if (threadIdx.x == 0 && acc != 0.0f) atomicAdd(out, acc);
}

// ---------------------------------------------------------------------------
// kCD: type 0 = C (warp->p2 kNN5: chamfer1 + curvature), type 1 = D (p2->warp NN).
// ---------------------------------------------------------------------------
__global__ void __launch_bounds__(TB)
kCD(float* __restrict__ out) {
    const int   NS[4]   = {8192, 4096, 2048, 1024};
    const int   SOFF[4] = {0, 16384, 24576, 28672};
    const float AB[4]   = {0.01f, 0.02f, 0.04f, 0.08f};
    int bx = blockIdx.x;
    int s, rel;
    if      (bx < 2048) { s = 0; rel = bx; }
    else if (bx < 3072) { s = 1; rel = bx - 2048; }
    else if (bx < 3584) { s = 2; rel = bx - 3072; }
    else                { s = 3; rel = bx - 3584; }
    const int N = NS[s];
    const int perType = N >> 3;
    int type = rel / perType;
    int blk = rel - type * perType;

    int lane = threadIdx.x & 31, w = threadIdx.x >> 5;
    int qg = blk * 16 + w * 2;
    int b = (qg >= N);
    int n0 = qg - (b ? N : 0);
    int base = SOFF[s] + (b ? N : 0);
    int grp = (s * 2 + b) * 3;

    __shared__ float acc;
    if (threadIdx.x == 0) acc = 0.0f;
    __syncthreads();
    float contrib = 0.0f;

    if (type == 0) {
        // C: queries warp (s1 order), refs p2
        const float4* R = g_s2 + base;
        const float4* Wq = g_s1w + base;
        const int* bs = g_binstart + (grp + 1) * NBIN2;
        float4 q0 = Wq[n0], q1 = Wq[n0 + 1];
        int st = __ldg(&bs[slabOf(q0.x) * YB + ybinOf(q0.y)]);
        float d0, d1; int p0, p1v;
        windowKNN2D<5>(R, N, bs, lane, q0, q1, st, d0, p0, d1, p1v);

        const float w_ch = AB[s], w_cv = 0.3f * AB[s];
#pragma unroll
        for (int qq = 0; qq < 2; ++qq) {
            float dd = qq ? d1 : d0;
            int pp = qq ? p1v : p0;
            float dist1 = __shfl_sync(FULLM, dd, 0);
            float wgt = 0.0f;
            float4 cc = make_float4(0.f, 0.f, 0.f, 0.f);
            if (lane < 5) {
                wgt = 1.0f / (dd + 1e-8f);
                cc = __ldg(&g_cv2[base + pp]);
            }
            float wsum = wsum32(wgt);
            float px = 0.f, py = 0.f, pz = 0.f;
            if (lane < 5) {
                float ww = wgt / wsum;
                px = ww * cc.x; py = ww * cc.y; pz = ww * cc.z;
            }
            float ix = wsum32(px), iy = wsum32(py), iz = wsum32(pz);
            if (lane == 0) {
                float4 cw = g_cvw[base + n0 + qq];
                float ex = ix - cw.x, ey = iy - cw.y, ez = iz - cw.z;
                float curv = fmaf(ex, ex, fmaf(ey, ey, ez * ez));
                contrib += w_ch * dist1 + w_cv * curv;
            }
        }
    } else {
        // D: queries p2, refs warp
        const float4* R = g_sw + base;
        const float4* Q = g_s2 + base;
        const int* bs = g_binstart + (grp + 2) * NBIN2;
        float4 q0 = Q[n0], q1 = Q[n0 + 1];
        int st = __ldg(&bs[slabOf(q0.x) * YB + ybinOf(q0.y)]);
        float d0, d1; int p0, p1v;
        windowKNN2D<1>(R, N, bs, lane, q0, q1, st, d0, p0, d1, p1v);
        float m0 = __shfl_sync(FULLM, d0, 0);
        float m1 = __shfl_sync(FULLM, d1, 0);
        if (lane == 0) contrib = AB[s] * (m0 + m1);
    }

    if (lane == 0 && contrib != 0.0f) atomicAdd(&acc, contrib);
    __syncthreads();
    if (threadIdx.x == 0 && acc != 0.0f) atomicAdd(out, acc);
}

// ---------------------------------------------------------------------------

extern "C" void kernel_launch(void* const* d_in, const int* in_sizes, int n_in,
                              void* d_out, int out_size) {
    float* out = (float*)d_out;
    InPtrs in;
    for (int i = 0; i < 12; ++i) in.p[i] = (const float*)d_in[i];

    kSortAll<<<24, 1024>>>(in, out);
    kAB<<<3840, TB>>>(out);
    kCD<<<3840, TB>>>(out);
}